// round 7
// baseline (speedup 1.0000x reference)
#include <cuda_runtime.h>
#include <cuda_bf16.h>
#include <cstdint>

#define BB   32
#define CC   1024
#define NSEQ 256
#define DQ   64
#define EPS_BN 1e-5f

typedef unsigned long long u64;
typedef unsigned int u32;

// ---------------- scratch (static device memory) ----------------
__device__ __nv_bfloat16 g_x_hi[(size_t)BB * CC * NSEQ];    // 16 MB  x[b][c][n]
__device__ __nv_bfloat16 g_x_lo[(size_t)BB * CC * NSEQ];    // 16 MB
__device__ __nv_bfloat16 g_xT_hi[(size_t)BB * NSEQ * CC];   // 16 MB  x^T[b][n][c]
__device__ __nv_bfloat16 g_wv_hi[(size_t)CC * CC];          //  2 MB
__device__ __nv_bfloat16 g_wqk_hi[128 * NSEQ];              // 64 KB  [Wq;Wk]
__device__ __nv_bfloat16 g_wqk_lo[128 * NSEQ];
__device__ __nv_bfloat16 g_qT_hi[(size_t)BB * CC * DQ];     //  4 MB  q^T[b][d][o]
__device__ __nv_bfloat16 g_qT_lo[(size_t)BB * CC * DQ];
__device__ __nv_bfloat16 g_kT_hi[(size_t)BB * CC * DQ];
__device__ __nv_bfloat16 g_kT_lo[(size_t)BB * CC * DQ];
__device__ __nv_bfloat16 g_vT_hi[(size_t)BB * NSEQ * CC];   // 16 MB  v^T[b][n][o]

// ---------------- helpers ----------------
__device__ __forceinline__ u32 smem_u32(const void* p) {
    u32 a;
    asm("{ .reg .u64 t; cvta.to.shared.u64 t, %1; cvt.u32.u64 %0, t; }"
        : "=r"(a) : "l"(p));
    return a;
}
__device__ __forceinline__ void split_bf16(float v, __nv_bfloat16& h, __nv_bfloat16& l) {
    h = __float2bfloat16(v);
    l = __float2bfloat16(v - __bfloat162float(h));
}
__device__ __forceinline__ u32 cvt_bf16x2(float hi, float lo) {
    u32 d;
    asm("cvt.rn.bf16x2.f32 %0, %1, %2;" : "=r"(d) : "f"(hi), "f"(lo));
    return d;
}
__device__ __forceinline__ void cp16(u32 dst, const void* src) {
    asm volatile("cp.async.cg.shared.global [%0], [%1], 16;" :: "r"(dst), "l"(src));
}
__device__ __forceinline__ void cp_commit() {
    asm volatile("cp.async.commit_group;" ::: "memory");
}
__device__ __forceinline__ void cp_wait1() {
    asm volatile("cp.async.wait_group 1;" ::: "memory");
}
__device__ __forceinline__ void cp_wait0() {
    asm volatile("cp.async.wait_group 0;" ::: "memory");
}
__device__ __forceinline__ void ldsm4(u32 addr, u32& r0, u32& r1, u32& r2, u32& r3) {
    asm volatile("ldmatrix.sync.aligned.m8n8.x4.shared.b16 {%0,%1,%2,%3}, [%4];"
                 : "=r"(r0), "=r"(r1), "=r"(r2), "=r"(r3) : "r"(addr));
}
__device__ __forceinline__ void mma_bf16(float* c, const u32* a, u32 b0, u32 b1) {
    asm volatile(
        "mma.sync.aligned.m16n8k16.row.col.f32.bf16.bf16.f32 "
        "{%0,%1,%2,%3}, {%4,%5,%6,%7}, {%8,%9}, {%0,%1,%2,%3};"
        : "+f"(c[0]), "+f"(c[1]), "+f"(c[2]), "+f"(c[3])
        : "r"(a[0]), "r"(a[1]), "r"(a[2]), "r"(a[3]), "r"(b0), "r"(b1));
}

// =====================================================================
// convert kernels
// =====================================================================
__global__ void convert_x(const float* __restrict__ x)
{
    __shared__ float t[32][33];
    const int tx = threadIdx.x, ty = threadIdx.y;
    const int c0 = blockIdx.x * 32, n0 = blockIdx.y * 32, b = blockIdx.z;

#pragma unroll
    for (int r = 0; r < 4; r++) {
        int row = ty + r * 8;
        size_t off = ((size_t)b * CC + c0 + row) * NSEQ + n0 + tx;
        float v = x[off];
        t[row][tx] = v;
        __nv_bfloat16 h, l; split_bf16(v, h, l);
        g_x_hi[off] = h;
        g_x_lo[off] = l;
    }
    __syncthreads();
#pragma unroll
    for (int r = 0; r < 4; r++) {
        int nrow = ty + r * 8;
        g_xT_hi[((size_t)b * NSEQ + n0 + nrow) * CC + c0 + tx] =
            __float2bfloat16(t[tx][nrow]);
    }
}

__global__ __launch_bounds__(256) void convert_wv(const float* __restrict__ W)
{
    size_t i = (size_t)blockIdx.x * 256 + threadIdx.x;
    float4 v = ((const float4*)W)[i];
    __nv_bfloat162* hp = (__nv_bfloat162*)g_wv_hi;
    __nv_bfloat162 a; a.x = __float2bfloat16(v.x); a.y = __float2bfloat16(v.y);
    __nv_bfloat162 bq; bq.x = __float2bfloat16(v.z); bq.y = __float2bfloat16(v.w);
    hp[i * 2] = a; hp[i * 2 + 1] = bq;
}

__global__ __launch_bounds__(256) void convert_wqk(
    const float* __restrict__ Wq, const float* __restrict__ Wk)
{
    int r = blockIdx.x;
    const float* src = (r < 64) ? (Wq + (size_t)r * NSEQ) : (Wk + (size_t)(r - 64) * NSEQ);
    float v = src[threadIdx.x];
    __nv_bfloat16 h, l; split_bf16(v, h, l);
    g_wqk_hi[r * NSEQ + threadIdx.x] = h;
    g_wqk_lo[r * NSEQ + threadIdx.x] = l;
}

// =====================================================================
// unified mma.sync GEMM (MODE 0: qk 3-pass; MODE 2: v 1-pass)
// =====================================================================
template<int MODE, int PASSES, int KTOT>
__global__ void __launch_bounds__(256, 1) mma_gemm2(
    float* __restrict__ Cout, const float* __restrict__ xres,
    const float* __restrict__ gA, const float* __restrict__ bA,
    const float* __restrict__ mA, const float* __restrict__ vA,
    const float* __restrict__ gB, const float* __restrict__ bB,
    const float* __restrict__ mB, const float* __restrict__ vB,
    const float* __restrict__ alpha)
{
    constexpr int STAGE = (PASSES == 3) ? 98304 : ((PASSES == 2) ? 65536 : 49152);
    constexpr int BOFF  = (PASSES == 1) ? 16384 : 32768;
    constexpr int NSLAB = KTOT / 64;

    extern __shared__ __align__(1024) char smem[];
    const u32 sbase = smem_u32(smem);
    const int tid = threadIdx.x;
    const int b   = blockIdx.z;
    const int n0  = blockIdx.x * 256;
    const int m0  = blockIdx.y * 128;

    int lda, ldb;
    const __nv_bfloat16 *A_hi, *A_lo = nullptr, *B_hi, *B_lo = nullptr;
    if (MODE == 0) {
        A_hi = g_wqk_hi; A_lo = g_wqk_lo;
        B_hi = g_x_hi + (size_t)b * CC * NSEQ;
        B_lo = g_x_lo + (size_t)b * CC * NSEQ;
        lda = NSEQ; ldb = NSEQ;
    } else {
        A_hi = g_wv_hi;
        B_hi = g_xT_hi + (size_t)b * NSEQ * CC;
        lda = CC; ldb = CC;
    }

    auto load_slab = [&](int k0, int buf) {
        const u32 sb = sbase + buf * STAGE;
#pragma unroll
        for (int i = 0; i < 4; i++) {
            int idx = tid + i * 256;
            int row = idx >> 3, c = idx & 7;
            u32 dst = sb + row * 128 + ((c ^ (row & 7)) << 4);
            cp16(dst, A_hi + (size_t)(m0 + row) * lda + k0 + c * 8);
            if (PASSES >= 2)
                cp16(dst + 16384, A_lo + (size_t)(m0 + row) * lda + k0 + c * 8);
        }
#pragma unroll
        for (int i = 0; i < 8; i++) {
            int idx = tid + i * 256;
            int row = idx >> 3, c = idx & 7;
            u32 dst = sb + BOFF + row * 128 + ((c ^ (row & 7)) << 4);
            cp16(dst, B_hi + (size_t)(n0 + row) * ldb + k0 + c * 8);
            if (PASSES == 3)
                cp16(dst + 32768, B_lo + (size_t)(n0 + row) * ldb + k0 + c * 8);
        }
        cp_commit();
    };

    const int lane = tid & 31;
    const int lr   = lane & 7;
    const int sub  = lane >> 3;
    const int warp = tid >> 5;
    const int wm   = warp >> 2, wn = warp & 3;

    const int a_row = wm * 64 + lr + (sub & 1) * 8;
    const int a_cad = sub >> 1;
    const int b_row = wn * 64 + lr + (sub >> 1) * 8;
    const int b_cad = sub & 1;

    float acc[4][8][4];
#pragma unroll
    for (int i = 0; i < 4; i++)
#pragma unroll
        for (int j = 0; j < 8; j++)
#pragma unroll
            for (int e = 0; e < 4; e++) acc[i][j][e] = 0.f;

    load_slab(0, 0);

    for (int s = 0; s < NSLAB; s++) {
        if (s + 1 < NSLAB) { load_slab((s + 1) * 64, (s + 1) & 1); cp_wait1(); }
        else               { cp_wait0(); }
        __syncthreads();

        const u32 sb = sbase + (s & 1) * STAGE;
#pragma unroll
        for (int kk = 0; kk < 4; kk++) {
            u32 bh[4][4], bl[4][4];
#pragma unroll
            for (int np = 0; np < 4; np++) {
                u32 badr = sb + BOFF + (b_row + np * 16) * 128
                         + (((kk * 2 + b_cad) ^ lr) << 4);
                ldsm4(badr, bh[np][0], bh[np][1], bh[np][2], bh[np][3]);
                if (PASSES == 3)
                    ldsm4(badr + 32768, bl[np][0], bl[np][1], bl[np][2], bl[np][3]);
            }
#pragma unroll
            for (int mt = 0; mt < 4; mt++) {
                u32 ah[4], al[4];
                u32 aadr = sb + (a_row + mt * 16) * 128
                         + (((kk * 2 + a_cad) ^ lr) << 4);
                ldsm4(aadr, ah[0], ah[1], ah[2], ah[3]);
                if (PASSES >= 2)
                    ldsm4(aadr + 16384, al[0], al[1], al[2], al[3]);
#pragma unroll
                for (int np = 0; np < 4; np++) {
                    mma_bf16(acc[mt][2 * np],     ah, bh[np][0], bh[np][1]);
                    mma_bf16(acc[mt][2 * np + 1], ah, bh[np][2], bh[np][3]);
                    if (PASSES >= 2) {
                        mma_bf16(acc[mt][2 * np],     al, bh[np][0], bh[np][1]);
                        mma_bf16(acc[mt][2 * np + 1], al, bh[np][2], bh[np][3]);
                    }
                    if (PASSES == 3) {
                        mma_bf16(acc[mt][2 * np],     ah, bl[np][0], bl[np][1]);
                        mma_bf16(acc[mt][2 * np + 1], ah, bl[np][2], bl[np][3]);
                    }
                }
            }
        }
        __syncthreads();
    }

    // epilogue: bn + relu, transpose via smem, write bf16
    float sc[4][2], bs[4][2];
#pragma unroll
    for (int mt = 0; mt < 4; mt++)
#pragma unroll
        for (int h = 0; h < 2; h++) {
            int o = wm * 64 + mt * 16 + (lane >> 2) + h * 8;
            float g, be, mn, vr;
            if (MODE == 0) {
                if (o < 64) { g = gA[o]; be = bA[o]; mn = mA[o]; vr = vA[o]; }
                else        { g = gB[o - 64]; be = bB[o - 64]; mn = mB[o - 64]; vr = vB[o - 64]; }
            } else {
                int m = m0 + o;
                g = gA[m]; be = bA[m]; mn = mA[m]; vr = vA[m];
            }
            float s = g * rsqrtf(vr + EPS_BN);
            sc[mt][h] = s;
            bs[mt][h] = be - mn * s;
        }

    __nv_bfloat16* Th = (__nv_bfloat16*)smem;
    __nv_bfloat16* Tl = (__nv_bfloat16*)(smem + 69632);
    const int mloc = wm * 64 + (lane >> 2);
    const int nbas = wn * 64 + (lane & 3) * 2;
#pragma unroll
    for (int mt = 0; mt < 4; mt++)
#pragma unroll
        for (int jj = 0; jj < 8; jj++)
#pragma unroll
            for (int e = 0; e < 4; e++) {
                int h = e >> 1, col = e & 1;
                float val = fmaxf(acc[mt][jj][e] * sc[mt][h] + bs[mt][h], 0.f);
                int off = (nbas + jj * 8 + col) * 136 + mloc + mt * 16 + h * 8;
                if (MODE == 0) {
                    __nv_bfloat16 hi, lo; split_bf16(val, hi, lo);
                    Th[off] = hi;
                    Tl[off] = lo;
                } else {
                    Th[off] = __float2bfloat16(val);
                }
            }
    __syncthreads();

#pragma unroll
    for (int i = 0; i < 16; i++) {
        int idx = tid + i * 256;
        int n = idx >> 4, ch = idx & 15;
        uint4 hv = *(uint4*)&Th[n * 136 + ch * 8];
        if (MODE == 0) {
            uint4 lv = *(uint4*)&Tl[n * 136 + ch * 8];
            if (ch < 8) {
                size_t dst = ((size_t)b * CC + n0 + n) * DQ + ch * 8;
                *(uint4*)&g_qT_hi[dst] = hv;
                *(uint4*)&g_qT_lo[dst] = lv;
            } else {
                size_t dst = ((size_t)b * CC + n0 + n) * DQ + (ch - 8) * 8;
                *(uint4*)&g_kT_hi[dst] = hv;
                *(uint4*)&g_kT_lo[dst] = lv;
            }
        } else {
            size_t dst = ((size_t)b * NSEQ + n) * CC + m0 + ch * 8;
            *(uint4*)&g_vT_hi[dst] = hv;
        }
    }
}

// =====================================================================
// fused attention: sim (3-pass HMMA) + softmax + aff.vT + alpha*.+x
// CTA = 32 c-rows; K(sim)=64; per-warp d-split for the PV GEMM.
// smem: [0,8K) kT tiles / stats; [8K,72K) phase1 B bufs (2x64K -> to 139K)
//       phase3: B bufs 2x32K @8K..72K; reduce 8x8704B @73728..143360
// grid (CC/32, BB)
// =====================================================================
#define FS_SMEM 143360

__global__ void __launch_bounds__(256, 1) fused_attn(
    float* __restrict__ Cout, const float* __restrict__ xres,
    const float* __restrict__ alpha)
{
    extern __shared__ __align__(1024) char smem[];
    const u32 sbase = smem_u32(smem);
    const int tid  = threadIdx.x;
    const int lane = tid & 31;
    const int lr   = lane & 7;
    const int sub  = lane >> 3;
    const int w    = tid >> 5;
    const int b    = blockIdx.y;
    const int c0   = blockIdx.x * 32;

    const __nv_bfloat16* Ah = g_kT_hi + ((size_t)b * CC + c0) * DQ;
    const __nv_bfloat16* Al = g_kT_lo + ((size_t)b * CC + c0) * DQ;
    const __nv_bfloat16* Bh = g_qT_hi + (size_t)b * CC * DQ;
    const __nv_bfloat16* Bl = g_qT_lo + (size_t)b * CC * DQ;
    const __nv_bfloat16* Vt = g_vT_hi + (size_t)b * NSEQ * CC;

    const float al_ = alpha[0];

    auto load_slab_q = [&](int slab, int buf) {
        const u32 sb = sbase + 8192 + buf * 65536;
#pragma unroll
        for (int i = 0; i < 8; i++) {
            int idx = tid + i * 256;
            int row = idx >> 3, c = idx & 7;
            u32 dst = sb + row * 128 + ((c ^ (row & 7)) << 4);
            cp16(dst,         Bh + (size_t)(slab * 256 + row) * DQ + c * 8);
            cp16(dst + 32768, Bl + (size_t)(slab * 256 + row) * DQ + c * 8);
        }
        cp_commit();
    };
    // vT slab: 64 n-rows x 256 d-cols (32 KB), row stride 512B
    auto load_slab_v = [&](int nc, int s, int buf) {
        const u32 sb = sbase + 8192 + buf * 32768;
#pragma unroll
        for (int i = 0; i < 8; i++) {
            int idx = tid + i * 256;
            int row = idx >> 5, c = idx & 31;
            u32 dst = sb + row * 512 + ((c ^ (row & 7)) << 4);
            cp16(dst, Vt + (size_t)(nc * 64 + row) * CC + s * 256 + c * 8);
        }
        cp_commit();
    };

    // ---------------- phase 1: sim ----------------
    {
        int row = tid >> 3, c = tid & 7;
        u32 dst = sbase + row * 128 + ((c ^ (row & 7)) << 4);
        cp16(dst,        Ah + (size_t)row * DQ + c * 8);
        cp16(dst + 4096, Al + (size_t)row * DQ + c * 8);
    }
    load_slab_q(0, 0);

    const int a_row = lr + (sub & 1) * 8;
    const int a_cad = sub >> 1;
    const int b_row = lr + (sub >> 1) * 8;
    const int b_cad = sub & 1;

    float acc[2][16][4];
#pragma unroll
    for (int i = 0; i < 2; i++)
#pragma unroll
        for (int j = 0; j < 16; j++)
#pragma unroll
            for (int e = 0; e < 4; e++) acc[i][j][e] = 0.f;

    for (int s = 0; s < 4; s++) {
        if (s + 1 < 4) { load_slab_q(s + 1, (s + 1) & 1); cp_wait1(); }
        else           { cp_wait0(); }
        __syncthreads();

        const u32 sb = sbase + 8192 + (s & 1) * 65536;
#pragma unroll
        for (int kk = 0; kk < 4; kk++) {
            u32 ah[2][4], al[2][4];
#pragma unroll
            for (int mt = 0; mt < 2; mt++) {
                u32 aadr = sbase + (a_row + mt * 16) * 128
                         + (((kk * 2 + a_cad) ^ lr) << 4);
                ldsm4(aadr,        ah[mt][0], ah[mt][1], ah[mt][2], ah[mt][3]);
                ldsm4(aadr + 4096, al[mt][0], al[mt][1], al[mt][2], al[mt][3]);
            }
#pragma unroll
            for (int jt = 0; jt < 2; jt++) {
                u32 bh[4], bl[4];
                u32 badr = sb + (b_row + w * 32 + jt * 16) * 128
                         + (((kk * 2 + b_cad) ^ lr) << 4);
                ldsm4(badr,         bh[0], bh[1], bh[2], bh[3]);
                ldsm4(badr + 32768, bl[0], bl[1], bl[2], bl[3]);
                int jj = s * 4 + jt * 2;
#pragma unroll
                for (int mt = 0; mt < 2; mt++) {
                    mma_bf16(acc[mt][jj],     ah[mt], bh[0], bh[1]);
                    mma_bf16(acc[mt][jj + 1], ah[mt], bh[2], bh[3]);
                    mma_bf16(acc[mt][jj],     al[mt], bh[0], bh[1]);
                    mma_bf16(acc[mt][jj + 1], al[mt], bh[2], bh[3]);
                    mma_bf16(acc[mt][jj],     ah[mt], bl[0], bl[1]);
                    mma_bf16(acc[mt][jj + 1], ah[mt], bl[2], bl[3]);
                }
            }
        }
        __syncthreads();
    }

    // prefetch first vT slab while doing softmax stats
    load_slab_v(0, 0, 0);

    // ---------------- phase 2: softmax stats ----------------
    float* rs  = (float*)smem;                 // [32][8]
    float* fst = (float*)(smem + 1024);        // [32]

    float m[2][2];
#pragma unroll
    for (int mt = 0; mt < 2; mt++)
#pragma unroll
        for (int h = 0; h < 2; h++) {
            float mm = -1e30f;
#pragma unroll
            for (int jj = 0; jj < 16; jj++)
                mm = fmaxf(mm, fmaxf(-acc[mt][jj][2 * h], -acc[mt][jj][2 * h + 1]));
            m[mt][h] = mm;
        }
#pragma unroll
    for (int s = 1; s <= 2; s <<= 1) {
#pragma unroll
        for (int mt = 0; mt < 2; mt++)
#pragma unroll
            for (int h = 0; h < 2; h++)
                m[mt][h] = fmaxf(m[mt][h], __shfl_xor_sync(~0u, m[mt][h], s));
    }
    if ((lane & 3) == 0) {
#pragma unroll
        for (int mt = 0; mt < 2; mt++)
#pragma unroll
            for (int h = 0; h < 2; h++)
                rs[(mt * 16 + (lane >> 2) + h * 8) * 8 + w] = m[mt][h];
    }
    __syncthreads();
    if (tid < 32) {
        float v = rs[tid * 8];
#pragma unroll
        for (int i = 1; i < 8; i++) v = fmaxf(v, rs[tid * 8 + i]);
        fst[tid] = v;
    }
    __syncthreads();

    float sm[2][2];
#pragma unroll
    for (int mt = 0; mt < 2; mt++)
#pragma unroll
        for (int h = 0; h < 2; h++) {
            float fm = fst[mt * 16 + (lane >> 2) + h * 8];
            float ss = 0.f;
#pragma unroll
            for (int jj = 0; jj < 16; jj++) {
                float e0 = __expf(-acc[mt][jj][2 * h]     - fm);
                float e1 = __expf(-acc[mt][jj][2 * h + 1] - fm);
                acc[mt][jj][2 * h]     = e0;
                acc[mt][jj][2 * h + 1] = e1;
                ss += e0 + e1;
            }
            sm[mt][h] = ss;
        }
#pragma unroll
    for (int s = 1; s <= 2; s <<= 1) {
#pragma unroll
        for (int mt = 0; mt < 2; mt++)
#pragma unroll
            for (int h = 0; h < 2; h++)
                sm[mt][h] += __shfl_xor_sync(~0u, sm[mt][h], s);
    }
    __syncthreads();
    if ((lane & 3) == 0) {
#pragma unroll
        for (int mt = 0; mt < 2; mt++)
#pragma unroll
            for (int h = 0; h < 2; h++)
                rs[(mt * 16 + (lane >> 2) + h * 8) * 8 + w] = sm[mt][h];
    }
    __syncthreads();
    if (tid < 32) {
        float v = rs[tid * 8];
#pragma unroll
        for (int i = 1; i < 8; i++) v += rs[tid * 8 + i];
        fst[tid] = 1.0f / v;
    }
    __syncthreads();

    // ---------------- phase 2b: convert aff to A fragments (regs) ----------------
    // afrag[mt][u]: 16x16 A tile rows mt*16.., cols u -> K0 = (u>>1)*256 + w*32 + (u&1)*16
    u32 afrag[2][8][4];
    {
        const int grp = lane >> 2;
#pragma unroll
        for (int mt = 0; mt < 2; mt++) {
            float inv0 = fst[mt * 16 + grp];
            float inv1 = fst[mt * 16 + grp + 8];
#pragma unroll
            for (int u = 0; u < 8; u++) {
                afrag[mt][u][0] = cvt_bf16x2(acc[mt][2*u][1]   * inv0, acc[mt][2*u][0]   * inv0);
                afrag[mt][u][1] = cvt_bf16x2(acc[mt][2*u][3]   * inv1, acc[mt][2*u][2]   * inv1);
                afrag[mt][u][2] = cvt_bf16x2(acc[mt][2*u+1][1] * inv0, acc[mt][2*u+1][0] * inv0);
                afrag[mt][u][3] = cvt_bf16x2(acc[mt][2*u+1][3] * inv1, acc[mt][2*u+1][2] * inv1);
            }
        }
    }

    // ---------------- phase 3: out = alpha * (aff . vT) + x ----------------
    float* red = (float*)(smem + 73728);   // 8 warps x [32][68] floats
    const int grp = lane >> 2, qt = lane & 3;

    for (int nc = 0; nc < 4; nc++) {
        float cacc[2][8][4];
#pragma unroll
        for (int i = 0; i < 2; i++)
#pragma unroll
            for (int j = 0; j < 8; j++)
#pragma unroll
                for (int e = 0; e < 4; e++) cacc[i][j][e] = 0.f;

        for (int s = 0; s < 4; s++) {
            if (s + 1 < 4)      { load_slab_v(nc, s + 1, (s + 1) & 1); cp_wait1(); }
            else if (nc + 1 < 4){ load_slab_v(nc + 1, 0, 0);           cp_wait1(); }
            else                { cp_wait0(); }
            __syncthreads();

            const u32 sb = sbase + 8192 + (s & 1) * 32768;
#pragma unroll
            for (int jt = 0; jt < 2; jt++) {
                const int u = s * 2 + jt;
                u32 bh[4][4];
#pragma unroll
                for (int np = 0; np < 4; np++) {
                    u32 badr = sb + (lr + (sub >> 1) * 8 + np * 16) * 512
                             + (((w * 4 + jt * 2 + b_cad) ^ lr) << 4);
                    ldsm4(badr, bh[np][0], bh[np][1], bh[np][2], bh[np][3]);
                }
#pragma unroll
                for (int mt = 0; mt < 2; mt++)
#pragma unroll
                    for (int np = 0; np < 4; np++) {
                        mma_bf16(cacc[mt][2 * np],     afrag[mt][u], bh[np][0], bh[np][1]);
                        mma_bf16(cacc[mt][2 * np + 1], afrag[mt][u], bh[np][2], bh[np][3]);
                    }
            }
            __syncthreads();
        }

        // cross-warp reduce + epilogue
#pragma unroll
        for (int mt = 0; mt < 2; mt++)
#pragma unroll
            for (int nb = 0; nb < 8; nb++) {
                int r0 = mt * 16 + grp;
                int cl = nb * 8 + qt * 2;
                float2 v0; v0.x = cacc[mt][nb][0]; v0.y = cacc[mt][nb][1];
                float2 v1; v1.x = cacc[mt][nb][2]; v1.y = cacc[mt][nb][3];
                *(float2*)&red[w * 2176 + r0 * 68 + cl]       = v0;
                *(float2*)&red[w * 2176 + (r0 + 8) * 68 + cl] = v1;
            }
        __syncthreads();

        {
            int row = tid >> 3, cb = (tid & 7) * 8;
            float4 s0 = make_float4(0.f, 0.f, 0.f, 0.f);
            float4 s1 = make_float4(0.f, 0.f, 0.f, 0.f);
#pragma unroll
            for (int ww = 0; ww < 8; ww++) {
                float4 a = *(float4*)&red[ww * 2176 + row * 68 + cb];
                float4 c = *(float4*)&red[ww * 2176 + row * 68 + cb + 4];
                s0.x += a.x; s0.y += a.y; s0.z += a.z; s0.w += a.w;
                s1.x += c.x; s1.y += c.y; s1.z += c.z; s1.w += c.w;
            }
            size_t base = ((size_t)b * CC + c0 + row) * NSEQ + nc * 64 + cb;
            float4 x0 = *(const float4*)&xres[base];
            float4 x1 = *(const float4*)&xres[base + 4];
            float4 o0, o1;
            o0.x = al_ * s0.x + x0.x; o0.y = al_ * s0.y + x0.y;
            o0.z = al_ * s0.z + x0.z; o0.w = al_ * s0.w + x0.w;
            o1.x = al_ * s1.x + x1.x; o1.y = al_ * s1.y + x1.y;
            o1.z = al_ * s1.z + x1.z; o1.w = al_ * s1.w + x1.w;
            *(float4*)&Cout[base]     = o0;
            *(float4*)&Cout[base + 4] = o1;
        }
        __syncthreads();
    }
}

// =====================================================================
extern "C" void kernel_launch(void* const* d_in, const int* in_sizes, int n_in,
                              void* d_out, int out_size)
{
    const float* x    = (const float*)d_in[0];
    const float* Wq   = (const float*)d_in[1];
    const float* Wk   = (const float*)d_in[2];
    const float* Wv   = (const float*)d_in[3];
    const float* bn1g = (const float*)d_in[4];
    const float* bn1b = (const float*)d_in[5];
    const float* bn1m = (const float*)d_in[6];
    const float* bn1v = (const float*)d_in[7];
    const float* bn2g = (const float*)d_in[8];
    const float* bn2b = (const float*)d_in[9];
    const float* bn2m = (const float*)d_in[10];
    const float* bn2v = (const float*)d_in[11];
    const float* bn3g = (const float*)d_in[12];
    const float* bn3b = (const float*)d_in[13];
    const float* bn3m = (const float*)d_in[14];
    const float* bn3v = (const float*)d_in[15];
    const float* alpha= (const float*)d_in[16];
    float* out = (float*)d_out;

    cudaFuncSetAttribute(mma_gemm2<0,3,256>,  cudaFuncAttributeMaxDynamicSharedMemorySize, 196608);
    cudaFuncSetAttribute(mma_gemm2<2,1,1024>, cudaFuncAttributeMaxDynamicSharedMemorySize, 98304);
    cudaFuncSetAttribute(fused_attn,          cudaFuncAttributeMaxDynamicSharedMemorySize, FS_SMEM);

    convert_x<<<dim3(CC / 32, NSEQ / 32, BB), dim3(32, 8)>>>(x);
    convert_wv<<<CC * CC / 4 / 256, 256>>>(Wv);
    convert_wqk<<<128, 256>>>(Wq, Wk);

    // qk: q,k = relu(bn([Wq;Wk] . x^T)) -> qT/kT hi/lo
    mma_gemm2<0,3,256><<<dim3(4, 1, BB), 256, 196608>>>(
        nullptr, nullptr, bn1g, bn1b, bn1m, bn1v, bn2g, bn2b, bn2m, bn2v, nullptr);

    // v = relu(bn3(Wv . x)) -> vT_hi   (1-pass bf16)
    mma_gemm2<2,1,1024><<<dim3(1, 8, BB), 256, 98304>>>(
        nullptr, nullptr, bn3g, bn3b, bn3m, bn3v,
        nullptr, nullptr, nullptr, nullptr, nullptr);

    // fused: sim + softmax + aff.vT + alpha*.+x -> d_out
    fused_attn<<<dim3(CC / 32, BB), 256, FS_SMEM>>>(out, x, alpha);
}

// round 8
// speedup vs baseline: 1.0564x; 1.0564x over previous
#include <cuda_runtime.h>
#include <cuda_bf16.h>
#include <cstdint>

#define BB   32
#define CC   1024
#define NSEQ 256
#define DQ   64
#define EPS_BN 1e-5f

typedef unsigned long long u64;
typedef unsigned int u32;

// ---------------- scratch (static device memory) ----------------
__device__ __nv_bfloat16 g_x_hi[(size_t)BB * CC * NSEQ];    // 16 MB  x[b][c][n]
__device__ __nv_bfloat16 g_x_lo[(size_t)BB * CC * NSEQ];    // 16 MB
__device__ __nv_bfloat16 g_xT_hi[(size_t)BB * NSEQ * CC];   // 16 MB  x^T[b][n][c]
__device__ __nv_bfloat16 g_wv_hi[(size_t)CC * CC];          //  2 MB
__device__ __nv_bfloat16 g_wqk_hi[128 * NSEQ];              // 64 KB  [Wq;Wk]
__device__ __nv_bfloat16 g_wqk_lo[128 * NSEQ];
__device__ __nv_bfloat16 g_qT_hi[(size_t)BB * CC * DQ];     //  4 MB  q^T[b][d][o]
__device__ __nv_bfloat16 g_qT_lo[(size_t)BB * CC * DQ];
__device__ __nv_bfloat16 g_kT_hi[(size_t)BB * CC * DQ];
__device__ __nv_bfloat16 g_kT_lo[(size_t)BB * CC * DQ];
__device__ __nv_bfloat16 g_aff_hi[(size_t)BB * CC * CC];    // 64 MB
__device__ __nv_bfloat16 g_vT_hi[(size_t)BB * NSEQ * CC];   // 16 MB  v^T[b][n][o]

// ---------------- helpers ----------------
__device__ __forceinline__ u32 smem_u32(const void* p) {
    u32 a;
    asm("{ .reg .u64 t; cvta.to.shared.u64 t, %1; cvt.u32.u64 %0, t; }"
        : "=r"(a) : "l"(p));
    return a;
}
__device__ __forceinline__ void split_bf16(float v, __nv_bfloat16& h, __nv_bfloat16& l) {
    h = __float2bfloat16(v);
    l = __float2bfloat16(v - __bfloat162float(h));
}
__device__ __forceinline__ void cp16(u32 dst, const void* src) {
    asm volatile("cp.async.cg.shared.global [%0], [%1], 16;" :: "r"(dst), "l"(src));
}
__device__ __forceinline__ void cp_commit() {
    asm volatile("cp.async.commit_group;" ::: "memory");
}
__device__ __forceinline__ void cp_wait1() {
    asm volatile("cp.async.wait_group 1;" ::: "memory");
}
__device__ __forceinline__ void cp_wait0() {
    asm volatile("cp.async.wait_group 0;" ::: "memory");
}
__device__ __forceinline__ void ldsm4(u32 addr, u32& r0, u32& r1, u32& r2, u32& r3) {
    asm volatile("ldmatrix.sync.aligned.m8n8.x4.shared.b16 {%0,%1,%2,%3}, [%4];"
                 : "=r"(r0), "=r"(r1), "=r"(r2), "=r"(r3) : "r"(addr));
}
__device__ __forceinline__ void mma_bf16(float* c, const u32* a, u32 b0, u32 b1) {
    asm volatile(
        "mma.sync.aligned.m16n8k16.row.col.f32.bf16.bf16.f32 "
        "{%0,%1,%2,%3}, {%4,%5,%6,%7}, {%8,%9}, {%0,%1,%2,%3};"
        : "+f"(c[0]), "+f"(c[1]), "+f"(c[2]), "+f"(c[3])
        : "r"(a[0]), "r"(a[1]), "r"(a[2]), "r"(a[3]), "r"(b0), "r"(b1));
}

// =====================================================================
// convert kernels
// =====================================================================
__global__ void convert_x(const float* __restrict__ x)
{
    __shared__ float t[32][33];
    const int tx = threadIdx.x, ty = threadIdx.y;
    const int c0 = blockIdx.x * 32, n0 = blockIdx.y * 32, b = blockIdx.z;

#pragma unroll
    for (int r = 0; r < 4; r++) {
        int row = ty + r * 8;
        size_t off = ((size_t)b * CC + c0 + row) * NSEQ + n0 + tx;
        float v = x[off];
        t[row][tx] = v;
        __nv_bfloat16 h, l; split_bf16(v, h, l);
        g_x_hi[off] = h;
        g_x_lo[off] = l;
    }
    __syncthreads();
#pragma unroll
    for (int r = 0; r < 4; r++) {
        int nrow = ty + r * 8;
        g_xT_hi[((size_t)b * NSEQ + n0 + nrow) * CC + c0 + tx] =
            __float2bfloat16(t[tx][nrow]);
    }
}

__global__ __launch_bounds__(256) void convert_wv(const float* __restrict__ W)
{
    size_t i = (size_t)blockIdx.x * 256 + threadIdx.x;
    float4 v = ((const float4*)W)[i];
    __nv_bfloat162* hp = (__nv_bfloat162*)g_wv_hi;
    __nv_bfloat162 a; a.x = __float2bfloat16(v.x); a.y = __float2bfloat16(v.y);
    __nv_bfloat162 bq; bq.x = __float2bfloat16(v.z); bq.y = __float2bfloat16(v.w);
    hp[i * 2] = a; hp[i * 2 + 1] = bq;
}

__global__ __launch_bounds__(256) void convert_wqk(
    const float* __restrict__ Wq, const float* __restrict__ Wk)
{
    int r = blockIdx.x;
    const float* src = (r < 64) ? (Wq + (size_t)r * NSEQ) : (Wk + (size_t)(r - 64) * NSEQ);
    float v = src[threadIdx.x];
    __nv_bfloat16 h, l; split_bf16(v, h, l);
    g_wqk_hi[r * NSEQ + threadIdx.x] = h;
    g_wqk_lo[r * NSEQ + threadIdx.x] = l;
}

// =====================================================================
// qk GEMM (3-pass, 256 threads) — unchanged from R6
// =====================================================================
__global__ void __launch_bounds__(256, 1) qk_mma(
    const float* __restrict__ gA, const float* __restrict__ bA,
    const float* __restrict__ mA, const float* __restrict__ vA,
    const float* __restrict__ gB, const float* __restrict__ bB,
    const float* __restrict__ mB, const float* __restrict__ vB)
{
    constexpr int STAGE = 98304;
    constexpr int BOFF  = 32768;

    extern __shared__ __align__(1024) char smem[];
    const u32 sbase = smem_u32(smem);
    const int tid = threadIdx.x;
    const int b   = blockIdx.z;
    const int n0  = blockIdx.x * 256;
    const int m0  = 0;

    const __nv_bfloat16 *A_hi = g_wqk_hi, *A_lo = g_wqk_lo;
    const __nv_bfloat16 *B_hi = g_x_hi + (size_t)b * CC * NSEQ;
    const __nv_bfloat16 *B_lo = g_x_lo + (size_t)b * CC * NSEQ;
    const int lda = NSEQ, ldb = NSEQ;

    auto load_slab = [&](int k0, int buf) {
        const u32 sb = sbase + buf * STAGE;
#pragma unroll
        for (int i = 0; i < 4; i++) {
            int idx = tid + i * 256;
            int row = idx >> 3, c = idx & 7;
            u32 dst = sb + row * 128 + ((c ^ (row & 7)) << 4);
            cp16(dst,         A_hi + (size_t)(m0 + row) * lda + k0 + c * 8);
            cp16(dst + 16384, A_lo + (size_t)(m0 + row) * lda + k0 + c * 8);
        }
#pragma unroll
        for (int i = 0; i < 8; i++) {
            int idx = tid + i * 256;
            int row = idx >> 3, c = idx & 7;
            u32 dst = sb + BOFF + row * 128 + ((c ^ (row & 7)) << 4);
            cp16(dst,         B_hi + (size_t)(n0 + row) * ldb + k0 + c * 8);
            cp16(dst + 32768, B_lo + (size_t)(n0 + row) * ldb + k0 + c * 8);
        }
        cp_commit();
    };

    const int lane = tid & 31;
    const int lr   = lane & 7;
    const int sub  = lane >> 3;
    const int warp = tid >> 5;
    const int wm   = warp >> 2, wn = warp & 3;

    const int a_row = wm * 64 + lr + (sub & 1) * 8;
    const int a_cad = sub >> 1;
    const int b_row = wn * 64 + lr + (sub >> 1) * 8;
    const int b_cad = sub & 1;

    float acc[4][8][4];
#pragma unroll
    for (int i = 0; i < 4; i++)
#pragma unroll
        for (int j = 0; j < 8; j++)
#pragma unroll
            for (int e = 0; e < 4; e++) acc[i][j][e] = 0.f;

    load_slab(0, 0);

    for (int s = 0; s < 4; s++) {
        if (s + 1 < 4) { load_slab((s + 1) * 64, (s + 1) & 1); cp_wait1(); }
        else           { cp_wait0(); }
        __syncthreads();

        const u32 sb = sbase + (s & 1) * STAGE;
#pragma unroll
        for (int kk = 0; kk < 4; kk++) {
            u32 bh[4][4], bl[4][4];
#pragma unroll
            for (int np = 0; np < 4; np++) {
                u32 badr = sb + BOFF + (b_row + np * 16) * 128
                         + (((kk * 2 + b_cad) ^ lr) << 4);
                ldsm4(badr,         bh[np][0], bh[np][1], bh[np][2], bh[np][3]);
                ldsm4(badr + 32768, bl[np][0], bl[np][1], bl[np][2], bl[np][3]);
            }
#pragma unroll
            for (int mt = 0; mt < 4; mt++) {
                u32 ah[4], al[4];
                u32 aadr = sb + (a_row + mt * 16) * 128
                         + (((kk * 2 + a_cad) ^ lr) << 4);
                ldsm4(aadr,         ah[0], ah[1], ah[2], ah[3]);
                ldsm4(aadr + 16384, al[0], al[1], al[2], al[3]);
#pragma unroll
                for (int np = 0; np < 4; np++) {
                    mma_bf16(acc[mt][2 * np],     ah, bh[np][0], bh[np][1]);
                    mma_bf16(acc[mt][2 * np + 1], ah, bh[np][2], bh[np][3]);
                    mma_bf16(acc[mt][2 * np],     al, bh[np][0], bh[np][1]);
                    mma_bf16(acc[mt][2 * np + 1], al, bh[np][2], bh[np][3]);
                    mma_bf16(acc[mt][2 * np],     ah, bl[np][0], bl[np][1]);
                    mma_bf16(acc[mt][2 * np + 1], ah, bl[np][2], bl[np][3]);
                }
            }
        }
        __syncthreads();
    }

    // epilogue: bn + relu, split, transpose via smem, write qT/kT hi/lo
    float sc[4][2], bs[4][2];
#pragma unroll
    for (int mt = 0; mt < 4; mt++)
#pragma unroll
        for (int h = 0; h < 2; h++) {
            int o = wm * 64 + mt * 16 + (lane >> 2) + h * 8;
            float g, be, mn, vr;
            if (o < 64) { g = gA[o]; be = bA[o]; mn = mA[o]; vr = vA[o]; }
            else        { g = gB[o - 64]; be = bB[o - 64]; mn = mB[o - 64]; vr = vB[o - 64]; }
            float s = g * rsqrtf(vr + EPS_BN);
            sc[mt][h] = s;
            bs[mt][h] = be - mn * s;
        }

    __nv_bfloat16* Th = (__nv_bfloat16*)smem;
    __nv_bfloat16* Tl = (__nv_bfloat16*)(smem + 69632);
    const int mloc = wm * 64 + (lane >> 2);
    const int nbas = wn * 64 + (lane & 3) * 2;
#pragma unroll
    for (int mt = 0; mt < 4; mt++)
#pragma unroll
        for (int jj = 0; jj < 8; jj++)
#pragma unroll
            for (int e = 0; e < 4; e++) {
                int h = e >> 1, col = e & 1;
                float val = fmaxf(acc[mt][jj][e] * sc[mt][h] + bs[mt][h], 0.f);
                int off = (nbas + jj * 8 + col) * 136 + mloc + mt * 16 + h * 8;
                __nv_bfloat16 hi, lo; split_bf16(val, hi, lo);
                Th[off] = hi;
                Tl[off] = lo;
            }
    __syncthreads();

#pragma unroll
    for (int i = 0; i < 16; i++) {
        int idx = tid + i * 256;
        int n = idx >> 4, ch = idx & 15;
        uint4 hv = *(uint4*)&Th[n * 136 + ch * 8];
        uint4 lv = *(uint4*)&Tl[n * 136 + ch * 8];
        if (ch < 8) {
            size_t dst = ((size_t)b * CC + n0 + n) * DQ + ch * 8;
            *(uint4*)&g_qT_hi[dst] = hv;
            *(uint4*)&g_qT_lo[dst] = lv;
        } else {
            size_t dst = ((size_t)b * CC + n0 + n) * DQ + (ch - 8) * 8;
            *(uint4*)&g_kT_hi[dst] = hv;
            *(uint4*)&g_kT_lo[dst] = lv;
        }
    }
}

// =====================================================================
// 1-pass bf16 GEMM, 512 threads (16 warps = 2M x 8N, warp tile 64x32)
// C tile 128 x 256, K=1024, slab=64, double buffered (96KB smem).
// MODE 2: v = relu(bn3(Wv_hi . xT_hi)) -> vT_hi (transposed store)
// MODE 3: out = alpha*(aff_hi . vT_hi) + x -> d_out
// grid (N/256, M/128, BB)
// =====================================================================
template<int MODE>
__global__ void __launch_bounds__(512, 1) mma_gemm512(
    float* __restrict__ Cout, const float* __restrict__ xres,
    const float* __restrict__ gA, const float* __restrict__ bA,
    const float* __restrict__ mA, const float* __restrict__ vA,
    const float* __restrict__ alpha)
{
    constexpr int STAGE = 49152;
    constexpr int BOFF  = 16384;

    extern __shared__ __align__(1024) char smem[];
    const u32 sbase = smem_u32(smem);
    const int tid = threadIdx.x;
    const int b   = blockIdx.z;
    const int n0  = blockIdx.x * 256;
    const int m0  = blockIdx.y * 128;

    const __nv_bfloat16 *A_hi, *B_hi;
    if (MODE == 2) {
        A_hi = g_wv_hi;
        B_hi = g_xT_hi + (size_t)b * NSEQ * CC;
    } else {
        A_hi = g_aff_hi + (size_t)b * CC * CC;
        B_hi = g_vT_hi + (size_t)b * NSEQ * CC;
    }

    auto load_slab = [&](int k0, int buf) {
        const u32 sb = sbase + buf * STAGE;
#pragma unroll
        for (int i = 0; i < 2; i++) {               // A: 128 rows x 8 chunks
            int idx = tid + i * 512;
            int row = idx >> 3, c = idx & 7;
            u32 dst = sb + row * 128 + ((c ^ (row & 7)) << 4);
            cp16(dst, A_hi + (size_t)(m0 + row) * CC + k0 + c * 8);
        }
#pragma unroll
        for (int i = 0; i < 4; i++) {               // B: 256 rows x 8 chunks
            int idx = tid + i * 512;
            int row = idx >> 3, c = idx & 7;
            u32 dst = sb + BOFF + row * 128 + ((c ^ (row & 7)) << 4);
            cp16(dst, B_hi + (size_t)(n0 + row) * CC + k0 + c * 8);
        }
        cp_commit();
    };

    const int lane = tid & 31;
    const int lr   = lane & 7;
    const int sub  = lane >> 3;
    const int warp = tid >> 5;
    const int wm   = warp >> 3, wn = warp & 7;

    const int a_row = wm * 64 + lr + (sub & 1) * 8;
    const int a_cad = sub >> 1;
    const int b_row = wn * 32 + lr + (sub >> 1) * 8;
    const int b_cad = sub & 1;

    float acc[4][4][4];
#pragma unroll
    for (int i = 0; i < 4; i++)
#pragma unroll
        for (int j = 0; j < 4; j++)
#pragma unroll
            for (int e = 0; e < 4; e++) acc[i][j][e] = 0.f;

    load_slab(0, 0);

    for (int s = 0; s < 16; s++) {
        if (s + 1 < 16) { load_slab((s + 1) * 64, (s + 1) & 1); cp_wait1(); }
        else            { cp_wait0(); }
        __syncthreads();

        const u32 sb = sbase + (s & 1) * STAGE;
#pragma unroll
        for (int kk = 0; kk < 4; kk++) {
            u32 bh[2][4];
#pragma unroll
            for (int np = 0; np < 2; np++) {
                u32 badr = sb + BOFF + (b_row + np * 16) * 128
                         + (((kk * 2 + b_cad) ^ lr) << 4);
                ldsm4(badr, bh[np][0], bh[np][1], bh[np][2], bh[np][3]);
            }
#pragma unroll
            for (int mt = 0; mt < 4; mt++) {
                u32 ah[4];
                u32 aadr = sb + (a_row + mt * 16) * 128
                         + (((kk * 2 + a_cad) ^ lr) << 4);
                ldsm4(aadr, ah[0], ah[1], ah[2], ah[3]);
#pragma unroll
                for (int np = 0; np < 2; np++) {
                    mma_bf16(acc[mt][2 * np],     ah, bh[np][0], bh[np][1]);
                    mma_bf16(acc[mt][2 * np + 1], ah, bh[np][2], bh[np][3]);
                }
            }
        }
        __syncthreads();
    }

    // ---------------- epilogues ----------------
    if (MODE == 3) {
        const float al_ = alpha[0];
#pragma unroll
        for (int mt = 0; mt < 4; mt++) {
            int m = m0 + wm * 64 + mt * 16 + (lane >> 2);
#pragma unroll
            for (int jj = 0; jj < 4; jj++) {
                int nn = n0 + wn * 32 + (lane & 3) * 2 + jj * 8;
                size_t b0i = ((size_t)b * CC + m) * NSEQ + nn;
                size_t b1i = b0i + 8 * NSEQ;
                float2 x0 = *(const float2*)&xres[b0i];
                float2 x1 = *(const float2*)&xres[b1i];
                float2 o0, o1;
                o0.x = al_ * acc[mt][jj][0] + x0.x;
                o0.y = al_ * acc[mt][jj][1] + x0.y;
                o1.x = al_ * acc[mt][jj][2] + x1.x;
                o1.y = al_ * acc[mt][jj][3] + x1.y;
                *(float2*)&Cout[b0i] = o0;
                *(float2*)&Cout[b1i] = o1;
            }
        }
        return;
    }

    // MODE 2: bn3 + relu, transpose via smem, write vT_hi bf16
    float sc[4][2], bs[4][2];
#pragma unroll
    for (int mt = 0; mt < 4; mt++)
#pragma unroll
        for (int h = 0; h < 2; h++) {
            int m = m0 + wm * 64 + mt * 16 + (lane >> 2) + h * 8;
            float s = gA[m] * rsqrtf(vA[m] + EPS_BN);
            sc[mt][h] = s;
            bs[mt][h] = bA[m] - mA[m] * s;
        }

    __nv_bfloat16* Th = (__nv_bfloat16*)smem;
    const int mloc = wm * 64 + (lane >> 2);
    const int nbas = wn * 32 + (lane & 3) * 2;
#pragma unroll
    for (int mt = 0; mt < 4; mt++)
#pragma unroll
        for (int jj = 0; jj < 4; jj++)
#pragma unroll
            for (int e = 0; e < 4; e++) {
                int h = e >> 1, col = e & 1;
                float val = fmaxf(acc[mt][jj][e] * sc[mt][h] + bs[mt][h], 0.f);
                int off = (nbas + jj * 8 + col) * 136 + mloc + mt * 16 + h * 8;
                Th[off] = __float2bfloat16(val);
            }
    __syncthreads();

#pragma unroll
    for (int i = 0; i < 8; i++) {
        int idx = tid + i * 512;
        int n = idx >> 4, ch = idx & 15;
        uint4 hv = *(uint4*)&Th[n * 136 + ch * 8];
        size_t dst = ((size_t)b * NSEQ + n0 + n) * CC + m0 + ch * 8;
        *(uint4*)&g_vT_hi[dst] = hv;
    }
}

// =====================================================================
// fused sim + softmax (R6 version): CTA = 32 c-rows x 1024 d, pipelined.
// grid (CC/32, BB)
// =====================================================================
#define FS_SMEM (8192 + 131072)

__global__ void __launch_bounds__(256, 1) sim_softmax_fused()
{
    extern __shared__ __align__(1024) char smem[];
    const u32 sbase = smem_u32(smem);
    const int tid  = threadIdx.x;
    const int lane = tid & 31;
    const int lr   = lane & 7;
    const int sub  = lane >> 3;
    const int w    = tid >> 5;
    const int b    = blockIdx.y;
    const int c0   = blockIdx.x * 32;

    const __nv_bfloat16* Ah = g_kT_hi + ((size_t)b * CC + c0) * DQ;
    const __nv_bfloat16* Al = g_kT_lo + ((size_t)b * CC + c0) * DQ;
    const __nv_bfloat16* Bh = g_qT_hi + (size_t)b * CC * DQ;
    const __nv_bfloat16* Bl = g_qT_lo + (size_t)b * CC * DQ;

    auto load_slab = [&](int slab, int buf) {
        const u32 sb = sbase + 8192 + buf * 65536;
#pragma unroll
        for (int i = 0; i < 8; i++) {
            int idx = tid + i * 256;
            int row = idx >> 3, c = idx & 7;
            u32 dst = sb + row * 128 + ((c ^ (row & 7)) << 4);
            cp16(dst,         Bh + (size_t)(slab * 256 + row) * DQ + c * 8);
            cp16(dst + 32768, Bl + (size_t)(slab * 256 + row) * DQ + c * 8);
        }
        cp_commit();
    };

    {
        int row = tid >> 3, c = tid & 7;
        u32 dst = sbase + row * 128 + ((c ^ (row & 7)) << 4);
        cp16(dst,        Ah + (size_t)row * DQ + c * 8);
        cp16(dst + 4096, Al + (size_t)row * DQ + c * 8);
    }
    load_slab(0, 0);

    const int a_row = lr + (sub & 1) * 8;
    const int a_cad = sub >> 1;
    const int b_row = lr + (sub >> 1) * 8;
    const int b_cad = sub & 1;

    float acc[2][16][4];
#pragma unroll
    for (int i = 0; i < 2; i++)
#pragma unroll
        for (int j = 0; j < 16; j++)
#pragma unroll
            for (int e = 0; e < 4; e++) acc[i][j][e] = 0.f;

    for (int s = 0; s < 4; s++) {
        if (s + 1 < 4) { load_slab(s + 1, (s + 1) & 1); cp_wait1(); }
        else           { cp_wait0(); }
        __syncthreads();

        const u32 sb = sbase + 8192 + (s & 1) * 65536;
#pragma unroll
        for (int kk = 0; kk < 4; kk++) {
            u32 ah[2][4], al[2][4];
#pragma unroll
            for (int mt = 0; mt < 2; mt++) {
                u32 aadr = sbase + (a_row + mt * 16) * 128
                         + (((kk * 2 + a_cad) ^ lr) << 4);
                ldsm4(aadr,        ah[mt][0], ah[mt][1], ah[mt][2], ah[mt][3]);
                ldsm4(aadr + 4096, al[mt][0], al[mt][1], al[mt][2], al[mt][3]);
            }
#pragma unroll
            for (int jt = 0; jt < 2; jt++) {
                u32 bh[4], bl[4];
                u32 badr = sb + (b_row + w * 32 + jt * 16) * 128
                         + (((kk * 2 + b_cad) ^ lr) << 4);
                ldsm4(badr,         bh[0], bh[1], bh[2], bh[3]);
                ldsm4(badr + 32768, bl[0], bl[1], bl[2], bl[3]);
                int jj = s * 4 + jt * 2;
#pragma unroll
                for (int mt = 0; mt < 2; mt++) {
                    mma_bf16(acc[mt][jj],     ah[mt], bh[0], bh[1]);
                    mma_bf16(acc[mt][jj + 1], ah[mt], bh[2], bh[3]);
                    mma_bf16(acc[mt][jj],     al[mt], bh[0], bh[1]);
                    mma_bf16(acc[mt][jj + 1], al[mt], bh[2], bh[3]);
                    mma_bf16(acc[mt][jj],     ah[mt], bl[0], bl[1]);
                    mma_bf16(acc[mt][jj + 1], ah[mt], bl[2], bl[3]);
                }
            }
        }
        __syncthreads();
    }

    float* rs  = (float*)smem;
    float* fst = (float*)(smem + 1024);

    float m[2][2];
#pragma unroll
    for (int mt = 0; mt < 2; mt++)
#pragma unroll
        for (int h = 0; h < 2; h++) {
            float mm = -1e30f;
#pragma unroll
            for (int jj = 0; jj < 16; jj++)
                mm = fmaxf(mm, fmaxf(-acc[mt][jj][2 * h], -acc[mt][jj][2 * h + 1]));
            m[mt][h] = mm;
        }
#pragma unroll
    for (int s = 1; s <= 2; s <<= 1) {
#pragma unroll
        for (int mt = 0; mt < 2; mt++)
#pragma unroll
            for (int h = 0; h < 2; h++)
                m[mt][h] = fmaxf(m[mt][h], __shfl_xor_sync(~0u, m[mt][h], s));
    }
    if ((lane & 3) == 0) {
#pragma unroll
        for (int mt = 0; mt < 2; mt++)
#pragma unroll
            for (int h = 0; h < 2; h++)
                rs[(mt * 16 + (lane >> 2) + h * 8) * 8 + w] = m[mt][h];
    }
    __syncthreads();
    if (tid < 32) {
        float v = rs[tid * 8];
#pragma unroll
        for (int i = 1; i < 8; i++) v = fmaxf(v, rs[tid * 8 + i]);
        fst[tid] = v;
    }
    __syncthreads();

    float sm[2][2];
#pragma unroll
    for (int mt = 0; mt < 2; mt++)
#pragma unroll
        for (int h = 0; h < 2; h++) {
            float fm = fst[mt * 16 + (lane >> 2) + h * 8];
            float ss = 0.f;
#pragma unroll
            for (int jj = 0; jj < 16; jj++) {
                float e0 = __expf(-acc[mt][jj][2 * h]     - fm);
                float e1 = __expf(-acc[mt][jj][2 * h + 1] - fm);
                acc[mt][jj][2 * h]     = e0;
                acc[mt][jj][2 * h + 1] = e1;
                ss += e0 + e1;
            }
            sm[mt][h] = ss;
        }
#pragma unroll
    for (int s = 1; s <= 2; s <<= 1) {
#pragma unroll
        for (int mt = 0; mt < 2; mt++)
#pragma unroll
            for (int h = 0; h < 2; h++)
                sm[mt][h] += __shfl_xor_sync(~0u, sm[mt][h], s);
    }
    __syncthreads();
    if ((lane & 3) == 0) {
#pragma unroll
        for (int mt = 0; mt < 2; mt++)
#pragma unroll
            for (int h = 0; h < 2; h++)
                rs[(mt * 16 + (lane >> 2) + h * 8) * 8 + w] = sm[mt][h];
    }
    __syncthreads();
    if (tid < 32) {
        float v = rs[tid * 8];
#pragma unroll
        for (int i = 1; i < 8; i++) v += rs[tid * 8 + i];
        fst[tid] = 1.0f / v;
    }
    __syncthreads();

    __nv_bfloat16* st = (__nv_bfloat16*)(smem + 8192);
#pragma unroll
    for (int mt = 0; mt < 2; mt++)
#pragma unroll
        for (int h = 0; h < 2; h++) {
            int r = mt * 16 + (lane >> 2) + h * 8;
            float inv = fst[r];
#pragma unroll
            for (int jj = 0; jj < 16; jj++) {
                int col = (jj >> 2) * 256 + w * 32 + ((jj >> 1) & 1) * 16
                        + (jj & 1) * 8 + (lane & 3) * 2;
                __nv_bfloat162 p;
                p.x = __float2bfloat16(acc[mt][jj][2 * h] * inv);
                p.y = __float2bfloat16(acc[mt][jj][2 * h + 1] * inv);
                *(__nv_bfloat162*)&st[r * 1048 + col] = p;
            }
        }
    __syncthreads();

#pragma unroll
    for (int i = 0; i < 16; i++) {
        int idx = tid + i * 256;
        int row = idx >> 7, u4 = idx & 127;
        uint4 v = *(uint4*)&st[row * 1048 + u4 * 8];
        *(uint4*)&g_aff_hi[((size_t)b * CC + c0 + row) * CC + u4 * 8] = v;
    }
}

// =====================================================================
extern "C" void kernel_launch(void* const* d_in, const int* in_sizes, int n_in,
                              void* d_out, int out_size)
{
    const float* x    = (const float*)d_in[0];
    const float* Wq   = (const float*)d_in[1];
    const float* Wk   = (const float*)d_in[2];
    const float* Wv   = (const float*)d_in[3];
    const float* bn1g = (const float*)d_in[4];
    const float* bn1b = (const float*)d_in[5];
    const float* bn1m = (const float*)d_in[6];
    const float* bn1v = (const float*)d_in[7];
    const float* bn2g = (const float*)d_in[8];
    const float* bn2b = (const float*)d_in[9];
    const float* bn2m = (const float*)d_in[10];
    const float* bn2v = (const float*)d_in[11];
    const float* bn3g = (const float*)d_in[12];
    const float* bn3b = (const float*)d_in[13];
    const float* bn3m = (const float*)d_in[14];
    const float* bn3v = (const float*)d_in[15];
    const float* alpha= (const float*)d_in[16];
    float* out = (float*)d_out;

    cudaFuncSetAttribute(qk_mma,         cudaFuncAttributeMaxDynamicSharedMemorySize, 196608);
    cudaFuncSetAttribute(mma_gemm512<2>, cudaFuncAttributeMaxDynamicSharedMemorySize, 98304);
    cudaFuncSetAttribute(mma_gemm512<3>, cudaFuncAttributeMaxDynamicSharedMemorySize, 98304);
    cudaFuncSetAttribute(sim_softmax_fused, cudaFuncAttributeMaxDynamicSharedMemorySize, FS_SMEM);

    convert_x<<<dim3(CC / 32, NSEQ / 32, BB), dim3(32, 8)>>>(x);
    convert_wv<<<CC * CC / 4 / 256, 256>>>(Wv);
    convert_wqk<<<128, 256>>>(Wq, Wk);

    // qk: q,k = relu(bn([Wq;Wk] . x^T)) -> qT/kT hi/lo
    qk_mma<<<dim3(4, 1, BB), 256, 196608>>>(
        bn1g, bn1b, bn1m, bn1v, bn2g, bn2b, bn2m, bn2v);

    // v = relu(bn3(Wv . x)) -> vT_hi   (1-pass bf16, 512 threads)
    mma_gemm512<2><<<dim3(1, 8, BB), 512, 98304>>>(
        nullptr, nullptr, bn3g, bn3b, bn3m, bn3v, nullptr);

    // sim + softmax fused -> aff_hi
    sim_softmax_fused<<<dim3(CC / 32, BB), 256, FS_SMEM>>>();

    // out = alpha*(aff . v) + x   (1-pass bf16, 512 threads)
    mma_gemm512<3><<<dim3(1, 8, BB), 512, 98304>>>(
        out, x, nullptr, nullptr, nullptr, nullptr, alpha);
}

// round 9
// speedup vs baseline: 1.1184x; 1.0586x over previous
#include <cuda_runtime.h>
#include <cuda_bf16.h>
#include <cstdint>

#define BB   32
#define CC   1024
#define NSEQ 256
#define DQ   64
#define EPS_BN 1e-5f

typedef unsigned long long u64;
typedef unsigned int u32;

// ---------------- scratch (static device memory) ----------------
__device__ __nv_bfloat16 g_x_hi[(size_t)BB * CC * NSEQ];    // 16 MB  x[b][c][n]
__device__ __nv_bfloat16 g_x_lo[(size_t)BB * CC * NSEQ];    // 16 MB
__device__ __nv_bfloat16 g_xT_hi[(size_t)BB * NSEQ * CC];   // 16 MB  x^T[b][n][c]
__device__ __nv_bfloat16 g_wv_hi[(size_t)CC * CC];          //  2 MB
__device__ __nv_bfloat16 g_wqk_hi[128 * NSEQ];              // 64 KB  [Wq;Wk]
__device__ __nv_bfloat16 g_wqk_lo[128 * NSEQ];
__device__ __nv_bfloat16 g_qT_hi[(size_t)BB * CC * DQ];     //  4 MB  q^T[b][d][o]
__device__ __nv_bfloat16 g_qT_lo[(size_t)BB * CC * DQ];
__device__ __nv_bfloat16 g_kT_hi[(size_t)BB * CC * DQ];
__device__ __nv_bfloat16 g_kT_lo[(size_t)BB * CC * DQ];
__device__ __nv_bfloat16 g_aff_hi[(size_t)BB * CC * CC];    // 64 MB
__device__ __nv_bfloat16 g_vT_hi[(size_t)BB * NSEQ * CC];   // 16 MB  v^T[b][n][o]

// ---------------- helpers ----------------
__device__ __forceinline__ u32 smem_u32(const void* p) {
    u32 a;
    asm("{ .reg .u64 t; cvta.to.shared.u64 t, %1; cvt.u32.u64 %0, t; }"
        : "=r"(a) : "l"(p));
    return a;
}
__device__ __forceinline__ void split_bf16(float v, __nv_bfloat16& h, __nv_bfloat16& l) {
    h = __float2bfloat16(v);
    l = __float2bfloat16(v - __bfloat162float(h));
}
__device__ __forceinline__ void cp16(u32 dst, const void* src) {
    asm volatile("cp.async.cg.shared.global [%0], [%1], 16;" :: "r"(dst), "l"(src));
}
__device__ __forceinline__ void cp_commit() {
    asm volatile("cp.async.commit_group;" ::: "memory");
}
__device__ __forceinline__ void cp_wait1() {
    asm volatile("cp.async.wait_group 1;" ::: "memory");
}
__device__ __forceinline__ void cp_wait0() {
    asm volatile("cp.async.wait_group 0;" ::: "memory");
}
__device__ __forceinline__ void ldsm4(u32 addr, u32& r0, u32& r1, u32& r2, u32& r3) {
    asm volatile("ldmatrix.sync.aligned.m8n8.x4.shared.b16 {%0,%1,%2,%3}, [%4];"
                 : "=r"(r0), "=r"(r1), "=r"(r2), "=r"(r3) : "r"(addr));
}
__device__ __forceinline__ void mma_bf16(float* c, const u32* a, u32 b0, u32 b1) {
    asm volatile(
        "mma.sync.aligned.m16n8k16.row.col.f32.bf16.bf16.f32 "
        "{%0,%1,%2,%3}, {%4,%5,%6,%7}, {%8,%9}, {%0,%1,%2,%3};"
        : "+f"(c[0]), "+f"(c[1]), "+f"(c[2]), "+f"(c[3])
        : "r"(a[0]), "r"(a[1]), "r"(a[2]), "r"(a[3]), "r"(b0), "r"(b1));
}

// =====================================================================
// convert kernels
// =====================================================================
__global__ void convert_x(const float* __restrict__ x)
{
    __shared__ float t[32][33];
    const int tx = threadIdx.x, ty = threadIdx.y;
    const int c0 = blockIdx.x * 32, n0 = blockIdx.y * 32, b = blockIdx.z;

#pragma unroll
    for (int r = 0; r < 4; r++) {
        int row = ty + r * 8;
        size_t off = ((size_t)b * CC + c0 + row) * NSEQ + n0 + tx;
        float v = x[off];
        t[row][tx] = v;
        __nv_bfloat16 h, l; split_bf16(v, h, l);
        g_x_hi[off] = h;
        g_x_lo[off] = l;
    }
    __syncthreads();
#pragma unroll
    for (int r = 0; r < 4; r++) {
        int nrow = ty + r * 8;
        g_xT_hi[((size_t)b * NSEQ + n0 + nrow) * CC + c0 + tx] =
            __float2bfloat16(t[tx][nrow]);
    }
}

__global__ __launch_bounds__(256) void convert_wv(const float* __restrict__ W)
{
    size_t i = (size_t)blockIdx.x * 256 + threadIdx.x;
    float4 v = ((const float4*)W)[i];
    __nv_bfloat162* hp = (__nv_bfloat162*)g_wv_hi;
    __nv_bfloat162 a; a.x = __float2bfloat16(v.x); a.y = __float2bfloat16(v.y);
    __nv_bfloat162 bq; bq.x = __float2bfloat16(v.z); bq.y = __float2bfloat16(v.w);
    hp[i * 2] = a; hp[i * 2 + 1] = bq;
}

__global__ __launch_bounds__(256) void convert_wqk(
    const float* __restrict__ Wq, const float* __restrict__ Wk)
{
    int r = blockIdx.x;
    const float* src = (r < 64) ? (Wq + (size_t)r * NSEQ) : (Wk + (size_t)(r - 64) * NSEQ);
    float v = src[threadIdx.x];
    __nv_bfloat16 h, l; split_bf16(v, h, l);
    g_wqk_hi[r * NSEQ + threadIdx.x] = h;
    g_wqk_lo[r * NSEQ + threadIdx.x] = l;
}

// =====================================================================
// qk GEMM (3-pass, 256 threads) — unchanged
// =====================================================================
__global__ void __launch_bounds__(256, 1) qk_mma(
    const float* __restrict__ gA, const float* __restrict__ bA,
    const float* __restrict__ mA, const float* __restrict__ vA,
    const float* __restrict__ gB, const float* __restrict__ bB,
    const float* __restrict__ mB, const float* __restrict__ vB)
{
    constexpr int STAGE = 98304;
    constexpr int BOFF  = 32768;

    extern __shared__ __align__(1024) char smem[];
    const u32 sbase = smem_u32(smem);
    const int tid = threadIdx.x;
    const int b   = blockIdx.z;
    const int n0  = blockIdx.x * 256;
    const int m0  = 0;

    const __nv_bfloat16 *A_hi = g_wqk_hi, *A_lo = g_wqk_lo;
    const __nv_bfloat16 *B_hi = g_x_hi + (size_t)b * CC * NSEQ;
    const __nv_bfloat16 *B_lo = g_x_lo + (size_t)b * CC * NSEQ;
    const int lda = NSEQ, ldb = NSEQ;

    auto load_slab = [&](int k0, int buf) {
        const u32 sb = sbase + buf * STAGE;
#pragma unroll
        for (int i = 0; i < 4; i++) {
            int idx = tid + i * 256;
            int row = idx >> 3, c = idx & 7;
            u32 dst = sb + row * 128 + ((c ^ (row & 7)) << 4);
            cp16(dst,         A_hi + (size_t)(m0 + row) * lda + k0 + c * 8);
            cp16(dst + 16384, A_lo + (size_t)(m0 + row) * lda + k0 + c * 8);
        }
#pragma unroll
        for (int i = 0; i < 8; i++) {
            int idx = tid + i * 256;
            int row = idx >> 3, c = idx & 7;
            u32 dst = sb + BOFF + row * 128 + ((c ^ (row & 7)) << 4);
            cp16(dst,         B_hi + (size_t)(n0 + row) * ldb + k0 + c * 8);
            cp16(dst + 32768, B_lo + (size_t)(n0 + row) * ldb + k0 + c * 8);
        }
        cp_commit();
    };

    const int lane = tid & 31;
    const int lr   = lane & 7;
    const int sub  = lane >> 3;
    const int warp = tid >> 5;
    const int wm   = warp >> 2, wn = warp & 3;

    const int a_row = wm * 64 + lr + (sub & 1) * 8;
    const int a_cad = sub >> 1;
    const int b_row = wn * 64 + lr + (sub >> 1) * 8;
    const int b_cad = sub & 1;

    float acc[4][8][4];
#pragma unroll
    for (int i = 0; i < 4; i++)
#pragma unroll
        for (int j = 0; j < 8; j++)
#pragma unroll
            for (int e = 0; e < 4; e++) acc[i][j][e] = 0.f;

    load_slab(0, 0);

    for (int s = 0; s < 4; s++) {
        if (s + 1 < 4) { load_slab((s + 1) * 64, (s + 1) & 1); cp_wait1(); }
        else           { cp_wait0(); }
        __syncthreads();

        const u32 sb = sbase + (s & 1) * STAGE;
#pragma unroll
        for (int kk = 0; kk < 4; kk++) {
            u32 bh[4][4], bl[4][4];
#pragma unroll
            for (int np = 0; np < 4; np++) {
                u32 badr = sb + BOFF + (b_row + np * 16) * 128
                         + (((kk * 2 + b_cad) ^ lr) << 4);
                ldsm4(badr,         bh[np][0], bh[np][1], bh[np][2], bh[np][3]);
                ldsm4(badr + 32768, bl[np][0], bl[np][1], bl[np][2], bl[np][3]);
            }
#pragma unroll
            for (int mt = 0; mt < 4; mt++) {
                u32 ah[4], al[4];
                u32 aadr = sb + (a_row + mt * 16) * 128
                         + (((kk * 2 + a_cad) ^ lr) << 4);
                ldsm4(aadr,         ah[0], ah[1], ah[2], ah[3]);
                ldsm4(aadr + 16384, al[0], al[1], al[2], al[3]);
#pragma unroll
                for (int np = 0; np < 4; np++) {
                    mma_bf16(acc[mt][2 * np],     ah, bh[np][0], bh[np][1]);
                    mma_bf16(acc[mt][2 * np + 1], ah, bh[np][2], bh[np][3]);
                    mma_bf16(acc[mt][2 * np],     al, bh[np][0], bh[np][1]);
                    mma_bf16(acc[mt][2 * np + 1], al, bh[np][2], bh[np][3]);
                    mma_bf16(acc[mt][2 * np],     ah, bl[np][0], bl[np][1]);
                    mma_bf16(acc[mt][2 * np + 1], ah, bl[np][2], bl[np][3]);
                }
            }
        }
        __syncthreads();
    }

    float sc[4][2], bs[4][2];
#pragma unroll
    for (int mt = 0; mt < 4; mt++)
#pragma unroll
        for (int h = 0; h < 2; h++) {
            int o = wm * 64 + mt * 16 + (lane >> 2) + h * 8;
            float g, be, mn, vr;
            if (o < 64) { g = gA[o]; be = bA[o]; mn = mA[o]; vr = vA[o]; }
            else        { g = gB[o - 64]; be = bB[o - 64]; mn = mB[o - 64]; vr = vB[o - 64]; }
            float s = g * rsqrtf(vr + EPS_BN);
            sc[mt][h] = s;
            bs[mt][h] = be - mn * s;
        }

    __nv_bfloat16* Th = (__nv_bfloat16*)smem;
    __nv_bfloat16* Tl = (__nv_bfloat16*)(smem + 69632);
    const int mloc = wm * 64 + (lane >> 2);
    const int nbas = wn * 64 + (lane & 3) * 2;
#pragma unroll
    for (int mt = 0; mt < 4; mt++)
#pragma unroll
        for (int jj = 0; jj < 8; jj++)
#pragma unroll
            for (int e = 0; e < 4; e++) {
                int h = e >> 1, col = e & 1;
                float val = fmaxf(acc[mt][jj][e] * sc[mt][h] + bs[mt][h], 0.f);
                int off = (nbas + jj * 8 + col) * 136 + mloc + mt * 16 + h * 8;
                __nv_bfloat16 hi, lo; split_bf16(val, hi, lo);
                Th[off] = hi;
                Tl[off] = lo;
            }
    __syncthreads();

#pragma unroll
    for (int i = 0; i < 16; i++) {
        int idx = tid + i * 256;
        int n = idx >> 4, ch = idx & 15;
        uint4 hv = *(uint4*)&Th[n * 136 + ch * 8];
        uint4 lv = *(uint4*)&Tl[n * 136 + ch * 8];
        if (ch < 8) {
            size_t dst = ((size_t)b * CC + n0 + n) * DQ + ch * 8;
            *(uint4*)&g_qT_hi[dst] = hv;
            *(uint4*)&g_qT_lo[dst] = lv;
        } else {
            size_t dst = ((size_t)b * CC + n0 + n) * DQ + (ch - 8) * 8;
            *(uint4*)&g_kT_hi[dst] = hv;
            *(uint4*)&g_kT_lo[dst] = lv;
        }
    }
}

// =====================================================================
// 1-pass bf16 GEMM: 128 threads, 2 CTAs/SM, CTA tile 128x128,
// warp tile 64x64 (2x2 warps), K slab 64, double buffered (64KB smem).
// MODE 2: v = relu(bn3(Wv_hi . xT_hi)) -> vT_hi (transposed store)
// MODE 3: out = alpha*(aff_hi . vT_hi) + x -> d_out
// grid (NSEQ/128, CC/128, BB) = (2, 8, 32)
// =====================================================================
template<int MODE>
__global__ void __launch_bounds__(128, 2) mma_gemm128(
    float* __restrict__ Cout, const float* __restrict__ xres,
    const float* __restrict__ gA, const float* __restrict__ bA,
    const float* __restrict__ mA, const float* __restrict__ vA,
    const float* __restrict__ alpha)
{
    constexpr int STAGE = 32768;
    constexpr int BOFF  = 16384;

    extern __shared__ __align__(1024) char smem[];
    const u32 sbase = smem_u32(smem);
    const int tid = threadIdx.x;
    const int b   = blockIdx.z;
    const int n0  = blockIdx.x * 128;
    const int m0  = blockIdx.y * 128;

    const __nv_bfloat16 *A_hi, *B_hi;
    if (MODE == 2) {
        A_hi = g_wv_hi;
        B_hi = g_xT_hi + (size_t)b * NSEQ * CC;
    } else {
        A_hi = g_aff_hi + (size_t)b * CC * CC;
        B_hi = g_vT_hi + (size_t)b * NSEQ * CC;
    }

    auto load_slab = [&](int k0, int buf) {
        const u32 sb = sbase + buf * STAGE;
#pragma unroll
        for (int i = 0; i < 8; i++) {               // A: 128 rows x 8 chunks
            int idx = tid + i * 128;
            int row = idx >> 3, c = idx & 7;
            u32 dst = sb + row * 128 + ((c ^ (row & 7)) << 4);
            cp16(dst, A_hi + (size_t)(m0 + row) * CC + k0 + c * 8);
        }
#pragma unroll
        for (int i = 0; i < 8; i++) {               // B: 128 rows x 8 chunks
            int idx = tid + i * 128;
            int row = idx >> 3, c = idx & 7;
            u32 dst = sb + BOFF + row * 128 + ((c ^ (row & 7)) << 4);
            cp16(dst, B_hi + (size_t)(n0 + row) * CC + k0 + c * 8);
        }
        cp_commit();
    };

    const int lane = tid & 31;
    const int lr   = lane & 7;
    const int sub  = lane >> 3;
    const int warp = tid >> 5;        // 0..3
    const int wm   = warp >> 1, wn = warp & 1;

    const int a_row = wm * 64 + lr + (sub & 1) * 8;
    const int a_cad = sub >> 1;
    const int b_row = wn * 64 + lr + (sub >> 1) * 8;
    const int b_cad = sub & 1;

    float acc[4][8][4];
#pragma unroll
    for (int i = 0; i < 4; i++)
#pragma unroll
        for (int j = 0; j < 8; j++)
#pragma unroll
            for (int e = 0; e < 4; e++) acc[i][j][e] = 0.f;

    load_slab(0, 0);

    for (int s = 0; s < 16; s++) {
        if (s + 1 < 16) { load_slab((s + 1) * 64, (s + 1) & 1); cp_wait1(); }
        else            { cp_wait0(); }
        __syncthreads();

        const u32 sb = sbase + (s & 1) * STAGE;
#pragma unroll
        for (int kk = 0; kk < 4; kk++) {
            u32 bh[4][4];
#pragma unroll
            for (int np = 0; np < 4; np++) {
                u32 badr = sb + BOFF + (b_row + np * 16) * 128
                         + (((kk * 2 + b_cad) ^ lr) << 4);
                ldsm4(badr, bh[np][0], bh[np][1], bh[np][2], bh[np][3]);
            }
#pragma unroll
            for (int mt = 0; mt < 4; mt++) {
                u32 ah[4];
                u32 aadr = sb + (a_row + mt * 16) * 128
                         + (((kk * 2 + a_cad) ^ lr) << 4);
                ldsm4(aadr, ah[0], ah[1], ah[2], ah[3]);
#pragma unroll
                for (int np = 0; np < 4; np++) {
                    mma_bf16(acc[mt][2 * np],     ah, bh[np][0], bh[np][1]);
                    mma_bf16(acc[mt][2 * np + 1], ah, bh[np][2], bh[np][3]);
                }
            }
        }
        __syncthreads();
    }

    // ---------------- epilogues ----------------
    if (MODE == 3) {
        const float al_ = alpha[0];
#pragma unroll
        for (int mt = 0; mt < 4; mt++) {
            int m = m0 + wm * 64 + mt * 16 + (lane >> 2);
#pragma unroll
            for (int jj = 0; jj < 8; jj++) {
                int nn = n0 + wn * 64 + (lane & 3) * 2 + jj * 8;
                size_t b0i = ((size_t)b * CC + m) * NSEQ + nn;
                size_t b1i = b0i + 8 * NSEQ;
                float2 x0 = *(const float2*)&xres[b0i];
                float2 x1 = *(const float2*)&xres[b1i];
                float2 o0, o1;
                o0.x = al_ * acc[mt][jj][0] + x0.x;
                o0.y = al_ * acc[mt][jj][1] + x0.y;
                o1.x = al_ * acc[mt][jj][2] + x1.x;
                o1.y = al_ * acc[mt][jj][3] + x1.y;
                *(float2*)&Cout[b0i] = o0;
                *(float2*)&Cout[b1i] = o1;
            }
        }
        return;
    }

    // MODE 2: bn3 + relu, transpose via smem, write vT_hi bf16
    float sc[4][2], bs[4][2];
#pragma unroll
    for (int mt = 0; mt < 4; mt++)
#pragma unroll
        for (int h = 0; h < 2; h++) {
            int m = m0 + wm * 64 + mt * 16 + (lane >> 2) + h * 8;
            float s = gA[m] * rsqrtf(vA[m] + EPS_BN);
            sc[mt][h] = s;
            bs[mt][h] = bA[m] - mA[m] * s;
        }

    __nv_bfloat16* Th = (__nv_bfloat16*)smem;       // [128 n][136 m] bf16
    const int mloc = wm * 64 + (lane >> 2);
    const int nbas = wn * 64 + (lane & 3) * 2;
#pragma unroll
    for (int mt = 0; mt < 4; mt++)
#pragma unroll
        for (int jj = 0; jj < 8; jj++)
#pragma unroll
            for (int e = 0; e < 4; e++) {
                int h = e >> 1, col = e & 1;
                float val = fmaxf(acc[mt][jj][e] * sc[mt][h] + bs[mt][h], 0.f);
                int off = (nbas + jj * 8 + col) * 136 + mloc + mt * 16 + h * 8;
                Th[off] = __float2bfloat16(val);
            }
    __syncthreads();

#pragma unroll
    for (int i = 0; i < 16; i++) {
        int idx = tid + i * 128;
        int n = idx >> 4, ch = idx & 15;
        uint4 hv = *(uint4*)&Th[n * 136 + ch * 8];
        size_t dst = ((size_t)b * NSEQ + n0 + n) * CC + m0 + ch * 8;
        *(uint4*)&g_vT_hi[dst] = hv;
    }
}

// =====================================================================
// fused sim + softmax: CTA = 32 c-rows x 1024 d, pipelined (unchanged)
// =====================================================================
#define FS_SMEM (8192 + 131072)

__global__ void __launch_bounds__(256, 1) sim_softmax_fused()
{
    extern __shared__ __align__(1024) char smem[];
    const u32 sbase = smem_u32(smem);
    const int tid  = threadIdx.x;
    const int lane = tid & 31;
    const int lr   = lane & 7;
    const int sub  = lane >> 3;
    const int w    = tid >> 5;
    const int b    = blockIdx.y;
    const int c0   = blockIdx.x * 32;

    const __nv_bfloat16* Ah = g_kT_hi + ((size_t)b * CC + c0) * DQ;
    const __nv_bfloat16* Al = g_kT_lo + ((size_t)b * CC + c0) * DQ;
    const __nv_bfloat16* Bh = g_qT_hi + (size_t)b * CC * DQ;
    const __nv_bfloat16* Bl = g_qT_lo + (size_t)b * CC * DQ;

    auto load_slab = [&](int slab, int buf) {
        const u32 sb = sbase + 8192 + buf * 65536;
#pragma unroll
        for (int i = 0; i < 8; i++) {
            int idx = tid + i * 256;
            int row = idx >> 3, c = idx & 7;
            u32 dst = sb + row * 128 + ((c ^ (row & 7)) << 4);
            cp16(dst,         Bh + (size_t)(slab * 256 + row) * DQ + c * 8);
            cp16(dst + 32768, Bl + (size_t)(slab * 256 + row) * DQ + c * 8);
        }
        cp_commit();
    };

    {
        int row = tid >> 3, c = tid & 7;
        u32 dst = sbase + row * 128 + ((c ^ (row & 7)) << 4);
        cp16(dst,        Ah + (size_t)row * DQ + c * 8);
        cp16(dst + 4096, Al + (size_t)row * DQ + c * 8);
    }
    load_slab(0, 0);

    const int a_row = lr + (sub & 1) * 8;
    const int a_cad = sub >> 1;
    const int b_row = lr + (sub >> 1) * 8;
    const int b_cad = sub & 1;

    float acc[2][16][4];
#pragma unroll
    for (int i = 0; i < 2; i++)
#pragma unroll
        for (int j = 0; j < 16; j++)
#pragma unroll
            for (int e = 0; e < 4; e++) acc[i][j][e] = 0.f;

    for (int s = 0; s < 4; s++) {
        if (s + 1 < 4) { load_slab(s + 1, (s + 1) & 1); cp_wait1(); }
        else           { cp_wait0(); }
        __syncthreads();

        const u32 sb = sbase + 8192 + (s & 1) * 65536;
#pragma unroll
        for (int kk = 0; kk < 4; kk++) {
            u32 ah[2][4], al[2][4];
#pragma unroll
            for (int mt = 0; mt < 2; mt++) {
                u32 aadr = sbase + (a_row + mt * 16) * 128
                         + (((kk * 2 + a_cad) ^ lr) << 4);
                ldsm4(aadr,        ah[mt][0], ah[mt][1], ah[mt][2], ah[mt][3]);
                ldsm4(aadr + 4096, al[mt][0], al[mt][1], al[mt][2], al[mt][3]);
            }
#pragma unroll
            for (int jt = 0; jt < 2; jt++) {
                u32 bh[4], bl[4];
                u32 badr = sb + (b_row + w * 32 + jt * 16) * 128
                         + (((kk * 2 + b_cad) ^ lr) << 4);
                ldsm4(badr,         bh[0], bh[1], bh[2], bh[3]);
                ldsm4(badr + 32768, bl[0], bl[1], bl[2], bl[3]);
                int jj = s * 4 + jt * 2;
#pragma unroll
                for (int mt = 0; mt < 2; mt++) {
                    mma_bf16(acc[mt][jj],     ah[mt], bh[0], bh[1]);
                    mma_bf16(acc[mt][jj + 1], ah[mt], bh[2], bh[3]);
                    mma_bf16(acc[mt][jj],     al[mt], bh[0], bh[1]);
                    mma_bf16(acc[mt][jj + 1], al[mt], bh[2], bh[3]);
                    mma_bf16(acc[mt][jj],     ah[mt], bl[0], bl[1]);
                    mma_bf16(acc[mt][jj + 1], ah[mt], bl[2], bl[3]);
                }
            }
        }
        __syncthreads();
    }

    float* rs  = (float*)smem;
    float* fst = (float*)(smem + 1024);

    float m[2][2];
#pragma unroll
    for (int mt = 0; mt < 2; mt++)
#pragma unroll
        for (int h = 0; h < 2; h++) {
            float mm = -1e30f;
#pragma unroll
            for (int jj = 0; jj < 16; jj++)
                mm = fmaxf(mm, fmaxf(-acc[mt][jj][2 * h], -acc[mt][jj][2 * h + 1]));
            m[mt][h] = mm;
        }
#pragma unroll
    for (int s = 1; s <= 2; s <<= 1) {
#pragma unroll
        for (int mt = 0; mt < 2; mt++)
#pragma unroll
            for (int h = 0; h < 2; h++)
                m[mt][h] = fmaxf(m[mt][h], __shfl_xor_sync(~0u, m[mt][h], s));
    }
    if ((lane & 3) == 0) {
#pragma unroll
        for (int mt = 0; mt < 2; mt++)
#pragma unroll
            for (int h = 0; h < 2; h++)
                rs[(mt * 16 + (lane >> 2) + h * 8) * 8 + w] = m[mt][h];
    }
    __syncthreads();
    if (tid < 32) {
        float v = rs[tid * 8];
#pragma unroll
        for (int i = 1; i < 8; i++) v = fmaxf(v, rs[tid * 8 + i]);
        fst[tid] = v;
    }
    __syncthreads();

    float sm[2][2];
#pragma unroll
    for (int mt = 0; mt < 2; mt++)
#pragma unroll
        for (int h = 0; h < 2; h++) {
            float fm = fst[mt * 16 + (lane >> 2) + h * 8];
            float ss = 0.f;
#pragma unroll
            for (int jj = 0; jj < 16; jj++) {
                float e0 = __expf(-acc[mt][jj][2 * h]     - fm);
                float e1 = __expf(-acc[mt][jj][2 * h + 1] - fm);
                acc[mt][jj][2 * h]     = e0;
                acc[mt][jj][2 * h + 1] = e1;
                ss += e0 + e1;
            }
            sm[mt][h] = ss;
        }
#pragma unroll
    for (int s = 1; s <= 2; s <<= 1) {
#pragma unroll
        for (int mt = 0; mt < 2; mt++)
#pragma unroll
            for (int h = 0; h < 2; h++)
                sm[mt][h] += __shfl_xor_sync(~0u, sm[mt][h], s);
    }
    __syncthreads();
    if ((lane & 3) == 0) {
#pragma unroll
        for (int mt = 0; mt < 2; mt++)
#pragma unroll
            for (int h = 0; h < 2; h++)
                rs[(mt * 16 + (lane >> 2) + h * 8) * 8 + w] = sm[mt][h];
    }
    __syncthreads();
    if (tid < 32) {
        float v = rs[tid * 8];
#pragma unroll
        for (int i = 1; i < 8; i++) v += rs[tid * 8 + i];
        fst[tid] = 1.0f / v;
    }
    __syncthreads();

    __nv_bfloat16* st = (__nv_bfloat16*)(smem + 8192);
#pragma unroll
    for (int mt = 0; mt < 2; mt++)
#pragma unroll
        for (int h = 0; h < 2; h++) {
            int r = mt * 16 + (lane >> 2) + h * 8;
            float inv = fst[r];
#pragma unroll
            for (int jj = 0; jj < 16; jj++) {
                int col = (jj >> 2) * 256 + w * 32 + ((jj >> 1) & 1) * 16
                        + (jj & 1) * 8 + (lane & 3) * 2;
                __nv_bfloat162 p;
                p.x = __float2bfloat16(acc[mt][jj][2 * h] * inv);
                p.y = __float2bfloat16(acc[mt][jj][2 * h + 1] * inv);
                *(__nv_bfloat162*)&st[r * 1048 + col] = p;
            }
        }
    __syncthreads();

#pragma unroll
    for (int i = 0; i < 16; i++) {
        int idx = tid + i * 256;
        int row = idx >> 7, u4 = idx & 127;
        uint4 v = *(uint4*)&st[row * 1048 + u4 * 8];
        *(uint4*)&g_aff_hi[((size_t)b * CC + c0 + row) * CC + u4 * 8] = v;
    }
}

// =====================================================================
extern "C" void kernel_launch(void* const* d_in, const int* in_sizes, int n_in,
                              void* d_out, int out_size)
{
    const float* x    = (const float*)d_in[0];
    const float* Wq   = (const float*)d_in[1];
    const float* Wk   = (const float*)d_in[2];
    const float* Wv   = (const float*)d_in[3];
    const float* bn1g = (const float*)d_in[4];
    const float* bn1b = (const float*)d_in[5];
    const float* bn1m = (const float*)d_in[6];
    const float* bn1v = (const float*)d_in[7];
    const float* bn2g = (const float*)d_in[8];
    const float* bn2b = (const float*)d_in[9];
    const float* bn2m = (const float*)d_in[10];
    const float* bn2v = (const float*)d_in[11];
    const float* bn3g = (const float*)d_in[12];
    const float* bn3b = (const float*)d_in[13];
    const float* bn3m = (const float*)d_in[14];
    const float* bn3v = (const float*)d_in[15];
    const float* alpha= (const float*)d_in[16];
    float* out = (float*)d_out;

    cudaFuncSetAttribute(qk_mma,          cudaFuncAttributeMaxDynamicSharedMemorySize, 196608);
    cudaFuncSetAttribute(mma_gemm128<2>,  cudaFuncAttributeMaxDynamicSharedMemorySize, 65536);
    cudaFuncSetAttribute(mma_gemm128<3>,  cudaFuncAttributeMaxDynamicSharedMemorySize, 65536);
    cudaFuncSetAttribute(sim_softmax_fused, cudaFuncAttributeMaxDynamicSharedMemorySize, FS_SMEM);

    convert_x<<<dim3(CC / 32, NSEQ / 32, BB), dim3(32, 8)>>>(x);
    convert_wv<<<CC * CC / 4 / 256, 256>>>(Wv);
    convert_wqk<<<128, 256>>>(Wq, Wk);

    // qk: q,k = relu(bn([Wq;Wk] . x^T)) -> qT/kT hi/lo
    qk_mma<<<dim3(4, 1, BB), 256, 196608>>>(
        bn1g, bn1b, bn1m, bn1v, bn2g, bn2b, bn2m, bn2v);

    // v = relu(bn3(Wv . x)) -> vT_hi   (1-pass, 128 thr, 2 CTAs/SM)
    mma_gemm128<2><<<dim3(NSEQ / 128, CC / 128, BB), 128, 65536>>>(
        nullptr, nullptr, bn3g, bn3b, bn3m, bn3v, nullptr);

    // sim + softmax fused -> aff_hi
    sim_softmax_fused<<<dim3(CC / 32, BB), 256, FS_SMEM>>>();

    // out = alpha*(aff . v) + x   (1-pass, 128 thr, 2 CTAs/SM)
    mma_gemm128<3><<<dim3(NSEQ / 128, CC / 128, BB), 128, 65536>>>(
        out, x, nullptr, nullptr, nullptr, nullptr, alpha);
}

// round 10
// speedup vs baseline: 1.1522x; 1.0302x over previous
#include <cuda_runtime.h>
#include <cuda_bf16.h>
#include <cstdint>

#define BB   32
#define CC   1024
#define NSEQ 256
#define DQ   64
#define EPS_BN 1e-5f

typedef unsigned long long u64;
typedef unsigned int u32;

// ---------------- scratch (static device memory) ----------------
__device__ __nv_bfloat16 g_x_hi[(size_t)BB * CC * NSEQ];    // 16 MB  x[b][c][n]
__device__ __nv_bfloat16 g_x_lo[(size_t)BB * CC * NSEQ];    // 16 MB
__device__ __nv_bfloat16 g_xT_hi[(size_t)BB * NSEQ * CC];   // 16 MB  x^T[b][n][c]
__device__ __nv_bfloat16 g_wv_hi[(size_t)CC * CC];          //  2 MB
__device__ __nv_bfloat16 g_wqk_hi[128 * NSEQ];              // 64 KB  [Wq;Wk]
__device__ __nv_bfloat16 g_wqk_lo[128 * NSEQ];
__device__ __nv_bfloat16 g_qT_hi[(size_t)BB * CC * DQ];     //  4 MB  q^T[b][d][o]
__device__ __nv_bfloat16 g_qT_lo[(size_t)BB * CC * DQ];
__device__ __nv_bfloat16 g_kT_hi[(size_t)BB * CC * DQ];
__device__ __nv_bfloat16 g_kT_lo[(size_t)BB * CC * DQ];
__device__ __nv_bfloat16 g_aff_hi[(size_t)BB * CC * CC];    // 64 MB  UNNORMALIZED exp
__device__ float         g_psum[(size_t)BB * CC * 8];       //  1 MB  row partial sums
__device__ __nv_bfloat16 g_vT_hi[(size_t)BB * NSEQ * CC];   // 16 MB  v^T[b][n][o]

// ---------------- helpers ----------------
__device__ __forceinline__ u32 smem_u32(const void* p) {
    u32 a;
    asm("{ .reg .u64 t; cvta.to.shared.u64 t, %1; cvt.u32.u64 %0, t; }"
        : "=r"(a) : "l"(p));
    return a;
}
__device__ __forceinline__ void split_bf16(float v, __nv_bfloat16& h, __nv_bfloat16& l) {
    h = __float2bfloat16(v);
    l = __float2bfloat16(v - __bfloat162float(h));
}
__device__ __forceinline__ void cp16(u32 dst, const void* src) {
    asm volatile("cp.async.cg.shared.global [%0], [%1], 16;" :: "r"(dst), "l"(src));
}
__device__ __forceinline__ void cp_commit() {
    asm volatile("cp.async.commit_group;" ::: "memory");
}
__device__ __forceinline__ void cp_wait1() {
    asm volatile("cp.async.wait_group 1;" ::: "memory");
}
__device__ __forceinline__ void cp_wait0() {
    asm volatile("cp.async.wait_group 0;" ::: "memory");
}
__device__ __forceinline__ void ldsm4(u32 addr, u32& r0, u32& r1, u32& r2, u32& r3) {
    asm volatile("ldmatrix.sync.aligned.m8n8.x4.shared.b16 {%0,%1,%2,%3}, [%4];"
                 : "=r"(r0), "=r"(r1), "=r"(r2), "=r"(r3) : "r"(addr));
}
__device__ __forceinline__ void mma_bf16(float* c, const u32* a, u32 b0, u32 b1) {
    asm volatile(
        "mma.sync.aligned.m16n8k16.row.col.f32.bf16.bf16.f32 "
        "{%0,%1,%2,%3}, {%4,%5,%6,%7}, {%8,%9}, {%0,%1,%2,%3};"
        : "+f"(c[0]), "+f"(c[1]), "+f"(c[2]), "+f"(c[3])
        : "r"(a[0]), "r"(a[1]), "r"(a[2]), "r"(a[3]), "r"(b0), "r"(b1));
}

// =====================================================================
// convert kernels
// =====================================================================
__global__ void convert_x(const float* __restrict__ x)
{
    __shared__ float t[32][33];
    const int tx = threadIdx.x, ty = threadIdx.y;
    const int c0 = blockIdx.x * 32, n0 = blockIdx.y * 32, b = blockIdx.z;

#pragma unroll
    for (int r = 0; r < 4; r++) {
        int row = ty + r * 8;
        size_t off = ((size_t)b * CC + c0 + row) * NSEQ + n0 + tx;
        float v = x[off];
        t[row][tx] = v;
        __nv_bfloat16 h, l; split_bf16(v, h, l);
        g_x_hi[off] = h;
        g_x_lo[off] = l;
    }
    __syncthreads();
#pragma unroll
    for (int r = 0; r < 4; r++) {
        int nrow = ty + r * 8;
        g_xT_hi[((size_t)b * NSEQ + n0 + nrow) * CC + c0 + tx] =
            __float2bfloat16(t[tx][nrow]);
    }
}

__global__ __launch_bounds__(256) void convert_wv(const float* __restrict__ W)
{
    size_t i = (size_t)blockIdx.x * 256 + threadIdx.x;
    float4 v = ((const float4*)W)[i];
    __nv_bfloat162* hp = (__nv_bfloat162*)g_wv_hi;
    __nv_bfloat162 a; a.x = __float2bfloat16(v.x); a.y = __float2bfloat16(v.y);
    __nv_bfloat162 bq; bq.x = __float2bfloat16(v.z); bq.y = __float2bfloat16(v.w);
    hp[i * 2] = a; hp[i * 2 + 1] = bq;
}

__global__ __launch_bounds__(256) void convert_wqk(
    const float* __restrict__ Wq, const float* __restrict__ Wk)
{
    int r = blockIdx.x;
    const float* src = (r < 64) ? (Wq + (size_t)r * NSEQ) : (Wk + (size_t)(r - 64) * NSEQ);
    float v = src[threadIdx.x];
    __nv_bfloat16 h, l; split_bf16(v, h, l);
    g_wqk_hi[r * NSEQ + threadIdx.x] = h;
    g_wqk_lo[r * NSEQ + threadIdx.x] = l;
}

// =====================================================================
// qk GEMM (3-pass, 256 threads) — unchanged
// =====================================================================
__global__ void __launch_bounds__(256, 1) qk_mma(
    const float* __restrict__ gA, const float* __restrict__ bA,
    const float* __restrict__ mA, const float* __restrict__ vA,
    const float* __restrict__ gB, const float* __restrict__ bB,
    const float* __restrict__ mB, const float* __restrict__ vB)
{
    constexpr int STAGE = 98304;
    constexpr int BOFF  = 32768;

    extern __shared__ __align__(1024) char smem[];
    const u32 sbase = smem_u32(smem);
    const int tid = threadIdx.x;
    const int b   = blockIdx.z;
    const int n0  = blockIdx.x * 256;
    const int m0  = 0;

    const __nv_bfloat16 *A_hi = g_wqk_hi, *A_lo = g_wqk_lo;
    const __nv_bfloat16 *B_hi = g_x_hi + (size_t)b * CC * NSEQ;
    const __nv_bfloat16 *B_lo = g_x_lo + (size_t)b * CC * NSEQ;
    const int lda = NSEQ, ldb = NSEQ;

    auto load_slab = [&](int k0, int buf) {
        const u32 sb = sbase + buf * STAGE;
#pragma unroll
        for (int i = 0; i < 4; i++) {
            int idx = tid + i * 256;
            int row = idx >> 3, c = idx & 7;
            u32 dst = sb + row * 128 + ((c ^ (row & 7)) << 4);
            cp16(dst,         A_hi + (size_t)(m0 + row) * lda + k0 + c * 8);
            cp16(dst + 16384, A_lo + (size_t)(m0 + row) * lda + k0 + c * 8);
        }
#pragma unroll
        for (int i = 0; i < 8; i++) {
            int idx = tid + i * 256;
            int row = idx >> 3, c = idx & 7;
            u32 dst = sb + BOFF + row * 128 + ((c ^ (row & 7)) << 4);
            cp16(dst,         B_hi + (size_t)(n0 + row) * ldb + k0 + c * 8);
            cp16(dst + 32768, B_lo + (size_t)(n0 + row) * ldb + k0 + c * 8);
        }
        cp_commit();
    };

    const int lane = tid & 31;
    const int lr   = lane & 7;
    const int sub  = lane >> 3;
    const int warp = tid >> 5;
    const int wm   = warp >> 2, wn = warp & 3;

    const int a_row = wm * 64 + lr + (sub & 1) * 8;
    const int a_cad = sub >> 1;
    const int b_row = wn * 64 + lr + (sub >> 1) * 8;
    const int b_cad = sub & 1;

    float acc[4][8][4];
#pragma unroll
    for (int i = 0; i < 4; i++)
#pragma unroll
        for (int j = 0; j < 8; j++)
#pragma unroll
            for (int e = 0; e < 4; e++) acc[i][j][e] = 0.f;

    load_slab(0, 0);

    for (int s = 0; s < 4; s++) {
        if (s + 1 < 4) { load_slab((s + 1) * 64, (s + 1) & 1); cp_wait1(); }
        else           { cp_wait0(); }
        __syncthreads();

        const u32 sb = sbase + (s & 1) * STAGE;
#pragma unroll
        for (int kk = 0; kk < 4; kk++) {
            u32 bh[4][4], bl[4][4];
#pragma unroll
            for (int np = 0; np < 4; np++) {
                u32 badr = sb + BOFF + (b_row + np * 16) * 128
                         + (((kk * 2 + b_cad) ^ lr) << 4);
                ldsm4(badr,         bh[np][0], bh[np][1], bh[np][2], bh[np][3]);
                ldsm4(badr + 32768, bl[np][0], bl[np][1], bl[np][2], bl[np][3]);
            }
#pragma unroll
            for (int mt = 0; mt < 4; mt++) {
                u32 ah[4], al[4];
                u32 aadr = sb + (a_row + mt * 16) * 128
                         + (((kk * 2 + a_cad) ^ lr) << 4);
                ldsm4(aadr,         ah[0], ah[1], ah[2], ah[3]);
                ldsm4(aadr + 16384, al[0], al[1], al[2], al[3]);
#pragma unroll
                for (int np = 0; np < 4; np++) {
                    mma_bf16(acc[mt][2 * np],     ah, bh[np][0], bh[np][1]);
                    mma_bf16(acc[mt][2 * np + 1], ah, bh[np][2], bh[np][3]);
                    mma_bf16(acc[mt][2 * np],     al, bh[np][0], bh[np][1]);
                    mma_bf16(acc[mt][2 * np + 1], al, bh[np][2], bh[np][3]);
                    mma_bf16(acc[mt][2 * np],     ah, bl[np][0], bl[np][1]);
                    mma_bf16(acc[mt][2 * np + 1], ah, bl[np][2], bl[np][3]);
                }
            }
        }
        __syncthreads();
    }

    float sc[4][2], bs[4][2];
#pragma unroll
    for (int mt = 0; mt < 4; mt++)
#pragma unroll
        for (int h = 0; h < 2; h++) {
            int o = wm * 64 + mt * 16 + (lane >> 2) + h * 8;
            float g, be, mn, vr;
            if (o < 64) { g = gA[o]; be = bA[o]; mn = mA[o]; vr = vA[o]; }
            else        { g = gB[o - 64]; be = bB[o - 64]; mn = mB[o - 64]; vr = vB[o - 64]; }
            float s = g * rsqrtf(vr + EPS_BN);
            sc[mt][h] = s;
            bs[mt][h] = be - mn * s;
        }

    __nv_bfloat16* Th = (__nv_bfloat16*)smem;
    __nv_bfloat16* Tl = (__nv_bfloat16*)(smem + 69632);
    const int mloc = wm * 64 + (lane >> 2);
    const int nbas = wn * 64 + (lane & 3) * 2;
#pragma unroll
    for (int mt = 0; mt < 4; mt++)
#pragma unroll
        for (int jj = 0; jj < 8; jj++)
#pragma unroll
            for (int e = 0; e < 4; e++) {
                int h = e >> 1, col = e & 1;
                float val = fmaxf(acc[mt][jj][e] * sc[mt][h] + bs[mt][h], 0.f);
                int off = (nbas + jj * 8 + col) * 136 + mloc + mt * 16 + h * 8;
                __nv_bfloat16 hi, lo; split_bf16(val, hi, lo);
                Th[off] = hi;
                Tl[off] = lo;
            }
    __syncthreads();

#pragma unroll
    for (int i = 0; i < 16; i++) {
        int idx = tid + i * 256;
        int n = idx >> 4, ch = idx & 15;
        uint4 hv = *(uint4*)&Th[n * 136 + ch * 8];
        uint4 lv = *(uint4*)&Tl[n * 136 + ch * 8];
        if (ch < 8) {
            size_t dst = ((size_t)b * CC + n0 + n) * DQ + ch * 8;
            *(uint4*)&g_qT_hi[dst] = hv;
            *(uint4*)&g_qT_lo[dst] = lv;
        } else {
            size_t dst = ((size_t)b * CC + n0 + n) * DQ + (ch - 8) * 8;
            *(uint4*)&g_kT_hi[dst] = hv;
            *(uint4*)&g_kT_lo[dst] = lv;
        }
    }
}

// =====================================================================
// sim_exp: 128x128 tile of exp(-kT.qT^T), 3-pass HMMA, K=64 single slab.
// Writes UNNORMALIZED exp (bf16) + per-(row, d-tile) partial sums.
// No max needed: sim >= 0 (q,k >= 0) so exp(-sim) <= 1.
// 128 threads, 2 CTAs/SM. grid (8 dtile, 8 ctile, BB)
// =====================================================================
__global__ void __launch_bounds__(128, 2) sim_exp()
{
    extern __shared__ __align__(1024) char smem[];
    const u32 sbase = smem_u32(smem);
    const int tid  = threadIdx.x;
    const int lane = tid & 31;
    const int lr   = lane & 7;
    const int sub  = lane >> 3;
    const int warp = tid >> 5;
    const int wm   = warp >> 1, wn = warp & 1;
    const int b    = blockIdx.z;
    const int c0   = blockIdx.y * 128;
    const int d0   = blockIdx.x * 128;

    const __nv_bfloat16* Ah = g_kT_hi + ((size_t)b * CC + c0) * DQ;
    const __nv_bfloat16* Al = g_kT_lo + ((size_t)b * CC + c0) * DQ;
    const __nv_bfloat16* Bh = g_qT_hi + ((size_t)b * CC + d0) * DQ;
    const __nv_bfloat16* Bl = g_qT_lo + ((size_t)b * CC + d0) * DQ;

    // load all operands (single K slab): A hi@0, A lo@16K, B hi@32K, B lo@48K
#pragma unroll
    for (int i = 0; i < 8; i++) {
        int idx = tid + i * 128;
        int row = idx >> 3, c = idx & 7;
        u32 dst = sbase + row * 128 + ((c ^ (row & 7)) << 4);
        cp16(dst,         Ah + (size_t)row * DQ + c * 8);
        cp16(dst + 16384, Al + (size_t)row * DQ + c * 8);
        cp16(dst + 32768, Bh + (size_t)row * DQ + c * 8);
        cp16(dst + 49152, Bl + (size_t)row * DQ + c * 8);
    }
    cp_commit();
    cp_wait0();
    __syncthreads();

    const int a_row = wm * 64 + lr + (sub & 1) * 8;
    const int a_cad = sub >> 1;
    const int b_row = wn * 64 + lr + (sub >> 1) * 8;
    const int b_cad = sub & 1;

    float acc[4][8][4];
#pragma unroll
    for (int i = 0; i < 4; i++)
#pragma unroll
        for (int j = 0; j < 8; j++)
#pragma unroll
            for (int e = 0; e < 4; e++) acc[i][j][e] = 0.f;

#pragma unroll
    for (int kk = 0; kk < 4; kk++) {
        u32 bh[4][4], bl[4][4];
#pragma unroll
        for (int np = 0; np < 4; np++) {
            u32 badr = sbase + 32768 + (b_row + np * 16) * 128
                     + (((kk * 2 + b_cad) ^ lr) << 4);
            ldsm4(badr,         bh[np][0], bh[np][1], bh[np][2], bh[np][3]);
            ldsm4(badr + 16384, bl[np][0], bl[np][1], bl[np][2], bl[np][3]);
        }
#pragma unroll
        for (int mt = 0; mt < 4; mt++) {
            u32 ah[4], al[4];
            u32 aadr = sbase + (a_row + mt * 16) * 128
                     + (((kk * 2 + a_cad) ^ lr) << 4);
            ldsm4(aadr,         ah[0], ah[1], ah[2], ah[3]);
            ldsm4(aadr + 16384, al[0], al[1], al[2], al[3]);
#pragma unroll
            for (int np = 0; np < 4; np++) {
                mma_bf16(acc[mt][2 * np],     ah, bh[np][0], bh[np][1]);
                mma_bf16(acc[mt][2 * np + 1], ah, bh[np][2], bh[np][3]);
                mma_bf16(acc[mt][2 * np],     al, bh[np][0], bh[np][1]);
                mma_bf16(acc[mt][2 * np + 1], al, bh[np][2], bh[np][3]);
                mma_bf16(acc[mt][2 * np],     ah, bl[np][0], bl[np][1]);
                mma_bf16(acc[mt][2 * np + 1], ah, bl[np][2], bl[np][3]);
            }
        }
    }
    __syncthreads();   // all ldsm done; smem reusable

    // ---- exp, row partial sums, stage bf16 ----
    __nv_bfloat16* st   = (__nv_bfloat16*)smem;        // [128][144] bf16 (stride 288B)
    float*         sums = (float*)(smem + 36864);      // [128][2]
    const int grp = lane >> 2, qt = lane & 3;

#pragma unroll
    for (int mt = 0; mt < 4; mt++)
#pragma unroll
        for (int h = 0; h < 2; h++) {
            int r = wm * 64 + mt * 16 + grp + h * 8;
            float s = 0.f;
#pragma unroll
            for (int jj = 0; jj < 8; jj++) {
                float e0 = __expf(-acc[mt][jj][2 * h]);
                float e1 = __expf(-acc[mt][jj][2 * h + 1]);
                s += e0 + e1;
                __nv_bfloat162 p;
                p.x = __float2bfloat16(e0);
                p.y = __float2bfloat16(e1);
                *(__nv_bfloat162*)&st[r * 144 + wn * 64 + jj * 8 + qt * 2] = p;
            }
            s += __shfl_xor_sync(~0u, s, 1);
            s += __shfl_xor_sync(~0u, s, 2);
            if (qt == 0) sums[r * 2 + wn] = s;
        }
    __syncthreads();

    // per-row partial sum for this d-tile (deterministic)
    {
        float S = sums[tid * 2] + sums[tid * 2 + 1];
        g_psum[((size_t)b * CC + c0 + tid) * 8 + blockIdx.x] = S;
    }

    // coalesced write of the exp tile
#pragma unroll
    for (int i = 0; i < 16; i++) {
        int idx = tid + i * 128;
        int row = idx >> 4, ch = idx & 15;
        uint4 v = *(uint4*)&st[row * 144 + ch * 8];
        *(uint4*)&g_aff_hi[((size_t)b * CC + c0 + row) * CC + d0 + ch * 8] = v;
    }
}

// =====================================================================
// 1-pass bf16 GEMM: 128 threads, 2 CTAs/SM, CTA tile 128x128.
// MODE 2: v = relu(bn3(Wv_hi . xT_hi)) -> vT_hi (transposed store)
// MODE 3: out = (alpha/S_m)*(exp . vT) + x -> d_out  (deferred softmax norm)
// grid (NSEQ/128 or CC/128, CC/128, BB)
// =====================================================================
template<int MODE>
__global__ void __launch_bounds__(128, 2) mma_gemm128(
    float* __restrict__ Cout, const float* __restrict__ xres,
    const float* __restrict__ gA, const float* __restrict__ bA,
    const float* __restrict__ mA, const float* __restrict__ vA,
    const float* __restrict__ alpha)
{
    constexpr int STAGE = 32768;
    constexpr int BOFF  = 16384;

    extern __shared__ __align__(1024) char smem[];
    const u32 sbase = smem_u32(smem);
    const int tid = threadIdx.x;
    const int b   = blockIdx.z;
    const int n0  = blockIdx.x * 128;
    const int m0  = blockIdx.y * 128;

    const __nv_bfloat16 *A_hi, *B_hi;
    if (MODE == 2) {
        A_hi = g_wv_hi;
        B_hi = g_xT_hi + (size_t)b * NSEQ * CC;
    } else {
        A_hi = g_aff_hi + (size_t)b * CC * CC;
        B_hi = g_vT_hi + (size_t)b * NSEQ * CC;
    }

    auto load_slab = [&](int k0, int buf) {
        const u32 sb = sbase + buf * STAGE;
#pragma unroll
        for (int i = 0; i < 8; i++) {
            int idx = tid + i * 128;
            int row = idx >> 3, c = idx & 7;
            u32 dst = sb + row * 128 + ((c ^ (row & 7)) << 4);
            cp16(dst, A_hi + (size_t)(m0 + row) * CC + k0 + c * 8);
        }
#pragma unroll
        for (int i = 0; i < 8; i++) {
            int idx = tid + i * 128;
            int row = idx >> 3, c = idx & 7;
            u32 dst = sb + BOFF + row * 128 + ((c ^ (row & 7)) << 4);
            cp16(dst, B_hi + (size_t)(n0 + row) * CC + k0 + c * 8);
        }
        cp_commit();
    };

    const int lane = tid & 31;
    const int lr   = lane & 7;
    const int sub  = lane >> 3;
    const int warp = tid >> 5;
    const int wm   = warp >> 1, wn = warp & 1;

    const int a_row = wm * 64 + lr + (sub & 1) * 8;
    const int a_cad = sub >> 1;
    const int b_row = wn * 64 + lr + (sub >> 1) * 8;
    const int b_cad = sub & 1;

    float acc[4][8][4];
#pragma unroll
    for (int i = 0; i < 4; i++)
#pragma unroll
        for (int j = 0; j < 8; j++)
#pragma unroll
            for (int e = 0; e < 4; e++) acc[i][j][e] = 0.f;

    load_slab(0, 0);

    for (int s = 0; s < 16; s++) {
        if (s + 1 < 16) { load_slab((s + 1) * 64, (s + 1) & 1); cp_wait1(); }
        else            { cp_wait0(); }
        __syncthreads();

        const u32 sb = sbase + (s & 1) * STAGE;
#pragma unroll
        for (int kk = 0; kk < 4; kk++) {
            u32 bh[4][4];
#pragma unroll
            for (int np = 0; np < 4; np++) {
                u32 badr = sb + BOFF + (b_row + np * 16) * 128
                         + (((kk * 2 + b_cad) ^ lr) << 4);
                ldsm4(badr, bh[np][0], bh[np][1], bh[np][2], bh[np][3]);
            }
#pragma unroll
            for (int mt = 0; mt < 4; mt++) {
                u32 ah[4];
                u32 aadr = sb + (a_row + mt * 16) * 128
                         + (((kk * 2 + a_cad) ^ lr) << 4);
                ldsm4(aadr, ah[0], ah[1], ah[2], ah[3]);
#pragma unroll
                for (int np = 0; np < 4; np++) {
                    mma_bf16(acc[mt][2 * np],     ah, bh[np][0], bh[np][1]);
                    mma_bf16(acc[mt][2 * np + 1], ah, bh[np][2], bh[np][3]);
                }
            }
        }
        __syncthreads();
    }

    // ---------------- epilogues ----------------
    if (MODE == 3) {
        const float al_ = alpha[0];
        float scl[4][2];
#pragma unroll
        for (int mt = 0; mt < 4; mt++)
#pragma unroll
            for (int h = 0; h < 2; h++) {
                int m = m0 + wm * 64 + mt * 16 + (lane >> 2) + h * 8;
                const float4* p = (const float4*)&g_psum[((size_t)b * CC + m) * 8];
                float4 u = p[0], v = p[1];
                float S = (u.x + u.y) + (u.z + u.w) + (v.x + v.y) + (v.z + v.w);
                scl[mt][h] = al_ / S;
            }
#pragma unroll
        for (int mt = 0; mt < 4; mt++) {
            int m = m0 + wm * 64 + mt * 16 + (lane >> 2);
#pragma unroll
            for (int jj = 0; jj < 8; jj++) {
                int nn = n0 + wn * 64 + (lane & 3) * 2 + jj * 8;
                size_t b0i = ((size_t)b * CC + m) * NSEQ + nn;
                size_t b1i = b0i + 8 * NSEQ;
                float2 x0 = *(const float2*)&xres[b0i];
                float2 x1 = *(const float2*)&xres[b1i];
                float2 o0, o1;
                o0.x = scl[mt][0] * acc[mt][jj][0] + x0.x;
                o0.y = scl[mt][0] * acc[mt][jj][1] + x0.y;
                o1.x = scl[mt][1] * acc[mt][jj][2] + x1.x;
                o1.y = scl[mt][1] * acc[mt][jj][3] + x1.y;
                *(float2*)&Cout[b0i] = o0;
                *(float2*)&Cout[b1i] = o1;
            }
        }
        return;
    }

    // MODE 2: bn3 + relu, transpose via smem, write vT_hi bf16
    float sc[4][2], bs[4][2];
#pragma unroll
    for (int mt = 0; mt < 4; mt++)
#pragma unroll
        for (int h = 0; h < 2; h++) {
            int m = m0 + wm * 64 + mt * 16 + (lane >> 2) + h * 8;
            float s = gA[m] * rsqrtf(vA[m] + EPS_BN);
            sc[mt][h] = s;
            bs[mt][h] = bA[m] - mA[m] * s;
        }

    __nv_bfloat16* Th = (__nv_bfloat16*)smem;       // [128 n][136 m] bf16
    const int mloc = wm * 64 + (lane >> 2);
    const int nbas = wn * 64 + (lane & 3) * 2;
#pragma unroll
    for (int mt = 0; mt < 4; mt++)
#pragma unroll
        for (int jj = 0; jj < 8; jj++)
#pragma unroll
            for (int e = 0; e < 4; e++) {
                int h = e >> 1, col = e & 1;
                float val = fmaxf(acc[mt][jj][e] * sc[mt][h] + bs[mt][h], 0.f);
                int off = (nbas + jj * 8 + col) * 136 + mloc + mt * 16 + h * 8;
                Th[off] = __float2bfloat16(val);
            }
    __syncthreads();

#pragma unroll
    for (int i = 0; i < 16; i++) {
        int idx = tid + i * 128;
        int n = idx >> 4, ch = idx & 15;
        uint4 hv = *(uint4*)&Th[n * 136 + ch * 8];
        size_t dst = ((size_t)b * NSEQ + n0 + n) * CC + m0 + ch * 8;
        *(uint4*)&g_vT_hi[dst] = hv;
    }
}

// =====================================================================
extern "C" void kernel_launch(void* const* d_in, const int* in_sizes, int n_in,
                              void* d_out, int out_size)
{
    const float* x    = (const float*)d_in[0];
    const float* Wq   = (const float*)d_in[1];
    const float* Wk   = (const float*)d_in[2];
    const float* Wv   = (const float*)d_in[3];
    const float* bn1g = (const float*)d_in[4];
    const float* bn1b = (const float*)d_in[5];
    const float* bn1m = (const float*)d_in[6];
    const float* bn1v = (const float*)d_in[7];
    const float* bn2g = (const float*)d_in[8];
    const float* bn2b = (const float*)d_in[9];
    const float* bn2m = (const float*)d_in[10];
    const float* bn2v = (const float*)d_in[11];
    const float* bn3g = (const float*)d_in[12];
    const float* bn3b = (const float*)d_in[13];
    const float* bn3m = (const float*)d_in[14];
    const float* bn3v = (const float*)d_in[15];
    const float* alpha= (const float*)d_in[16];
    float* out = (float*)d_out;

    cudaFuncSetAttribute(qk_mma,         cudaFuncAttributeMaxDynamicSharedMemorySize, 196608);
    cudaFuncSetAttribute(sim_exp,        cudaFuncAttributeMaxDynamicSharedMemorySize, 65536);
    cudaFuncSetAttribute(mma_gemm128<2>, cudaFuncAttributeMaxDynamicSharedMemorySize, 65536);
    cudaFuncSetAttribute(mma_gemm128<3>, cudaFuncAttributeMaxDynamicSharedMemorySize, 65536);

    convert_x<<<dim3(CC / 32, NSEQ / 32, BB), dim3(32, 8)>>>(x);
    convert_wv<<<CC * CC / 4 / 256, 256>>>(Wv);
    convert_wqk<<<128, 256>>>(Wq, Wk);

    // qk: q,k = relu(bn([Wq;Wk] . x^T)) -> qT/kT hi/lo
    qk_mma<<<dim3(4, 1, BB), 256, 196608>>>(
        bn1g, bn1b, bn1m, bn1v, bn2g, bn2b, bn2m, bn2v);

    // v = relu(bn3(Wv . x)) -> vT_hi   (1-pass, 128 thr, 2 CTAs/SM)
    mma_gemm128<2><<<dim3(NSEQ / 128, CC / 128, BB), 128, 65536>>>(
        nullptr, nullptr, bn3g, bn3b, bn3m, bn3v, nullptr);

    // sim: unnormalized exp(-kT.q) tiles + row partial sums
    sim_exp<<<dim3(CC / 128, CC / 128, BB), 128, 65536>>>();

    // out = (alpha/S)*(exp . vT) + x   (1-pass, 128 thr, 2 CTAs/SM)
    mma_gemm128<3><<<dim3(NSEQ / 128, CC / 128, BB), 128, 65536>>>(
        out, x, nullptr, nullptr, nullptr, nullptr, alpha);
}

// round 11
// speedup vs baseline: 1.1750x; 1.0198x over previous
#include <cuda_runtime.h>
#include <cuda_bf16.h>
#include <cstdint>

#define BB   32
#define CC   1024
#define NSEQ 256
#define DQ   64
#define EPS_BN 1e-5f

typedef unsigned long long u64;
typedef unsigned int u32;

// ---------------- scratch (static device memory) ----------------
__device__ __nv_bfloat16 g_x_hi[(size_t)BB * CC * NSEQ];    // 16 MB  x[b][c][n]
__device__ __nv_bfloat16 g_x_lo[(size_t)BB * CC * NSEQ];    // 16 MB
__device__ __nv_bfloat16 g_xT_hi[(size_t)BB * NSEQ * CC];   // 16 MB  x^T[b][n][c]
__device__ __nv_bfloat16 g_wv_hi[(size_t)CC * CC];          //  2 MB
__device__ __nv_bfloat16 g_wqk_hi[128 * NSEQ];              // 64 KB  [Wq;Wk]
__device__ __nv_bfloat16 g_wqk_lo[128 * NSEQ];
__device__ __nv_bfloat16 g_qT_hi[(size_t)BB * CC * DQ];     //  4 MB  q^T[b][d][o]
__device__ __nv_bfloat16 g_qT_lo[(size_t)BB * CC * DQ];
__device__ __nv_bfloat16 g_kT_hi[(size_t)BB * CC * DQ];
__device__ __nv_bfloat16 g_kT_lo[(size_t)BB * CC * DQ];
__device__ __nv_bfloat16 g_aff_hi[(size_t)BB * CC * CC];    // 64 MB  UNNORMALIZED exp
__device__ float         g_psum[(size_t)BB * CC * 8];       //  1 MB  row partial sums
__device__ __nv_bfloat16 g_vT_hi[(size_t)BB * NSEQ * CC];   // 16 MB  v^T[b][n][o]

// ---------------- helpers ----------------
__device__ __forceinline__ u32 smem_u32(const void* p) {
    u32 a;
    asm("{ .reg .u64 t; cvta.to.shared.u64 t, %1; cvt.u32.u64 %0, t; }"
        : "=r"(a) : "l"(p));
    return a;
}
__device__ __forceinline__ void split_bf16(float v, __nv_bfloat16& h, __nv_bfloat16& l) {
    h = __float2bfloat16(v);
    l = __float2bfloat16(v - __bfloat162float(h));
}
__device__ __forceinline__ void cp16(u32 dst, const void* src) {
    asm volatile("cp.async.cg.shared.global [%0], [%1], 16;" :: "r"(dst), "l"(src));
}
__device__ __forceinline__ void cp_commit() {
    asm volatile("cp.async.commit_group;" ::: "memory");
}
__device__ __forceinline__ void cp_wait1() {
    asm volatile("cp.async.wait_group 1;" ::: "memory");
}
__device__ __forceinline__ void cp_wait0() {
    asm volatile("cp.async.wait_group 0;" ::: "memory");
}
__device__ __forceinline__ void ldsm4(u32 addr, u32& r0, u32& r1, u32& r2, u32& r3) {
    asm volatile("ldmatrix.sync.aligned.m8n8.x4.shared.b16 {%0,%1,%2,%3}, [%4];"
                 : "=r"(r0), "=r"(r1), "=r"(r2), "=r"(r3) : "r"(addr));
}
__device__ __forceinline__ void mma_bf16(float* c, const u32* a, u32 b0, u32 b1) {
    asm volatile(
        "mma.sync.aligned.m16n8k16.row.col.f32.bf16.bf16.f32 "
        "{%0,%1,%2,%3}, {%4,%5,%6,%7}, {%8,%9}, {%0,%1,%2,%3};"
        : "+f"(c[0]), "+f"(c[1]), "+f"(c[2]), "+f"(c[3])
        : "r"(a[0]), "r"(a[1]), "r"(a[2]), "r"(a[3]), "r"(b0), "r"(b1));
}

// =====================================================================
// convert_all: one kernel, 1D grid dispatch.
//  blocks [0, 8192):      x -> x_hi/lo + xT_hi (32x32 tiles)
//  blocks [8192, 9216):   Wv -> wv_hi
//  blocks [9216, 9344):   Wq/Wk -> wqk hi/lo
// =====================================================================
__global__ __launch_bounds__(256) void convert_all(
    const float* __restrict__ x,  const float* __restrict__ W,
    const float* __restrict__ Wq, const float* __restrict__ Wk)
{
    __shared__ float t[32][33];
    const int bid = blockIdx.x, tid = threadIdx.x;

    if (bid < 8192) {
        const int tx = tid & 31, ty = tid >> 5;
        const int c0 = (bid & 31) * 32;
        const int n0 = ((bid >> 5) & 7) * 32;
        const int b  = bid >> 8;
#pragma unroll
        for (int r = 0; r < 4; r++) {
            int row = ty + r * 8;
            size_t off = ((size_t)b * CC + c0 + row) * NSEQ + n0 + tx;
            float v = x[off];
            t[row][tx] = v;
            __nv_bfloat16 h, l; split_bf16(v, h, l);
            g_x_hi[off] = h;
            g_x_lo[off] = l;
        }
        __syncthreads();
#pragma unroll
        for (int r = 0; r < 4; r++) {
            int nrow = ty + r * 8;
            g_xT_hi[((size_t)b * NSEQ + n0 + nrow) * CC + c0 + tx] =
                __float2bfloat16(t[tx][nrow]);
        }
    } else if (bid < 9216) {
        size_t i = (size_t)(bid - 8192) * 256 + tid;
        float4 v = ((const float4*)W)[i];
        __nv_bfloat162* hp = (__nv_bfloat162*)g_wv_hi;
        __nv_bfloat162 a; a.x = __float2bfloat16(v.x); a.y = __float2bfloat16(v.y);
        __nv_bfloat162 bq; bq.x = __float2bfloat16(v.z); bq.y = __float2bfloat16(v.w);
        hp[i * 2] = a; hp[i * 2 + 1] = bq;
    } else {
        int r = bid - 9216;
        const float* src = (r < 64) ? (Wq + (size_t)r * NSEQ)
                                    : (Wk + (size_t)(r - 64) * NSEQ);
        float v = src[tid];
        __nv_bfloat16 h, l; split_bf16(v, h, l);
        g_wqk_hi[r * NSEQ + tid] = h;
        g_wqk_lo[r * NSEQ + tid] = l;
    }
}

// =====================================================================
// qk GEMM (3-pass, 256 threads) — unchanged
// =====================================================================
__global__ void __launch_bounds__(256, 1) qk_mma(
    const float* __restrict__ gA, const float* __restrict__ bA,
    const float* __restrict__ mA, const float* __restrict__ vA,
    const float* __restrict__ gB, const float* __restrict__ bB,
    const float* __restrict__ mB, const float* __restrict__ vB)
{
    constexpr int STAGE = 98304;
    constexpr int BOFF  = 32768;

    extern __shared__ __align__(1024) char smem[];
    const u32 sbase = smem_u32(smem);
    const int tid = threadIdx.x;
    const int b   = blockIdx.z;
    const int n0  = blockIdx.x * 256;
    const int m0  = 0;

    const __nv_bfloat16 *A_hi = g_wqk_hi, *A_lo = g_wqk_lo;
    const __nv_bfloat16 *B_hi = g_x_hi + (size_t)b * CC * NSEQ;
    const __nv_bfloat16 *B_lo = g_x_lo + (size_t)b * CC * NSEQ;
    const int lda = NSEQ, ldb = NSEQ;

    auto load_slab = [&](int k0, int buf) {
        const u32 sb = sbase + buf * STAGE;
#pragma unroll
        for (int i = 0; i < 4; i++) {
            int idx = tid + i * 256;
            int row = idx >> 3, c = idx & 7;
            u32 dst = sb + row * 128 + ((c ^ (row & 7)) << 4);
            cp16(dst,         A_hi + (size_t)(m0 + row) * lda + k0 + c * 8);
            cp16(dst + 16384, A_lo + (size_t)(m0 + row) * lda + k0 + c * 8);
        }
#pragma unroll
        for (int i = 0; i < 8; i++) {
            int idx = tid + i * 256;
            int row = idx >> 3, c = idx & 7;
            u32 dst = sb + BOFF + row * 128 + ((c ^ (row & 7)) << 4);
            cp16(dst,         B_hi + (size_t)(n0 + row) * ldb + k0 + c * 8);
            cp16(dst + 32768, B_lo + (size_t)(n0 + row) * ldb + k0 + c * 8);
        }
        cp_commit();
    };

    const int lane = tid & 31;
    const int lr   = lane & 7;
    const int sub  = lane >> 3;
    const int warp = tid >> 5;
    const int wm   = warp >> 2, wn = warp & 3;

    const int a_row = wm * 64 + lr + (sub & 1) * 8;
    const int a_cad = sub >> 1;
    const int b_row = wn * 64 + lr + (sub >> 1) * 8;
    const int b_cad = sub & 1;

    float acc[4][8][4];
#pragma unroll
    for (int i = 0; i < 4; i++)
#pragma unroll
        for (int j = 0; j < 8; j++)
#pragma unroll
            for (int e = 0; e < 4; e++) acc[i][j][e] = 0.f;

    load_slab(0, 0);

    for (int s = 0; s < 4; s++) {
        if (s + 1 < 4) { load_slab((s + 1) * 64, (s + 1) & 1); cp_wait1(); }
        else           { cp_wait0(); }
        __syncthreads();

        const u32 sb = sbase + (s & 1) * STAGE;
#pragma unroll
        for (int kk = 0; kk < 4; kk++) {
            u32 bh[4][4], bl[4][4];
#pragma unroll
            for (int np = 0; np < 4; np++) {
                u32 badr = sb + BOFF + (b_row + np * 16) * 128
                         + (((kk * 2 + b_cad) ^ lr) << 4);
                ldsm4(badr,         bh[np][0], bh[np][1], bh[np][2], bh[np][3]);
                ldsm4(badr + 32768, bl[np][0], bl[np][1], bl[np][2], bl[np][3]);
            }
#pragma unroll
            for (int mt = 0; mt < 4; mt++) {
                u32 ah[4], al[4];
                u32 aadr = sb + (a_row + mt * 16) * 128
                         + (((kk * 2 + a_cad) ^ lr) << 4);
                ldsm4(aadr,         ah[0], ah[1], ah[2], ah[3]);
                ldsm4(aadr + 16384, al[0], al[1], al[2], al[3]);
#pragma unroll
                for (int np = 0; np < 4; np++) {
                    mma_bf16(acc[mt][2 * np],     ah, bh[np][0], bh[np][1]);
                    mma_bf16(acc[mt][2 * np + 1], ah, bh[np][2], bh[np][3]);
                    mma_bf16(acc[mt][2 * np],     al, bh[np][0], bh[np][1]);
                    mma_bf16(acc[mt][2 * np + 1], al, bh[np][2], bh[np][3]);
                    mma_bf16(acc[mt][2 * np],     ah, bl[np][0], bl[np][1]);
                    mma_bf16(acc[mt][2 * np + 1], ah, bl[np][2], bl[np][3]);
                }
            }
        }
        __syncthreads();
    }

    float sc[4][2], bs[4][2];
#pragma unroll
    for (int mt = 0; mt < 4; mt++)
#pragma unroll
        for (int h = 0; h < 2; h++) {
            int o = wm * 64 + mt * 16 + (lane >> 2) + h * 8;
            float g, be, mn, vr;
            if (o < 64) { g = gA[o]; be = bA[o]; mn = mA[o]; vr = vA[o]; }
            else        { g = gB[o - 64]; be = bB[o - 64]; mn = mB[o - 64]; vr = vB[o - 64]; }
            float s = g * rsqrtf(vr + EPS_BN);
            sc[mt][h] = s;
            bs[mt][h] = be - mn * s;
        }

    __nv_bfloat16* Th = (__nv_bfloat16*)smem;
    __nv_bfloat16* Tl = (__nv_bfloat16*)(smem + 69632);
    const int mloc = wm * 64 + (lane >> 2);
    const int nbas = wn * 64 + (lane & 3) * 2;
#pragma unroll
    for (int mt = 0; mt < 4; mt++)
#pragma unroll
        for (int jj = 0; jj < 8; jj++)
#pragma unroll
            for (int e = 0; e < 4; e++) {
                int h = e >> 1, col = e & 1;
                float val = fmaxf(acc[mt][jj][e] * sc[mt][h] + bs[mt][h], 0.f);
                int off = (nbas + jj * 8 + col) * 136 + mloc + mt * 16 + h * 8;
                __nv_bfloat16 hi, lo; split_bf16(val, hi, lo);
                Th[off] = hi;
                Tl[off] = lo;
            }
    __syncthreads();

#pragma unroll
    for (int i = 0; i < 16; i++) {
        int idx = tid + i * 256;
        int n = idx >> 4, ch = idx & 15;
        uint4 hv = *(uint4*)&Th[n * 136 + ch * 8];
        uint4 lv = *(uint4*)&Tl[n * 136 + ch * 8];
        if (ch < 8) {
            size_t dst = ((size_t)b * CC + n0 + n) * DQ + ch * 8;
            *(uint4*)&g_qT_hi[dst] = hv;
            *(uint4*)&g_qT_lo[dst] = lv;
        } else {
            size_t dst = ((size_t)b * CC + n0 + n) * DQ + (ch - 8) * 8;
            *(uint4*)&g_kT_hi[dst] = hv;
            *(uint4*)&g_kT_lo[dst] = lv;
        }
    }
}

// =====================================================================
// v_sim: merged kernel. 128 threads, 2 CTAs/SM, 64KB smem.
//  blockIdx.x < 2:  v tile   (n0 = bx*128, m0 = by*128)
//  blockIdx.x >= 2: sim tile (d0 = (bx-2)*128, c0 = by*128)
// grid (10, 8, BB)
// =====================================================================
__global__ void __launch_bounds__(128, 2) v_sim(
    const float* __restrict__ gA, const float* __restrict__ bA,
    const float* __restrict__ mA, const float* __restrict__ vA)
{
    extern __shared__ __align__(1024) char smem[];
    const u32 sbase = smem_u32(smem);
    const int tid  = threadIdx.x;
    const int lane = tid & 31;
    const int lr   = lane & 7;
    const int sub  = lane >> 3;
    const int warp = tid >> 5;
    const int wm   = warp >> 1, wn = warp & 1;
    const int b    = blockIdx.z;

    const int a_row = wm * 64 + lr + (sub & 1) * 8;
    const int a_cad = sub >> 1;
    const int b_row = wn * 64 + lr + (sub >> 1) * 8;
    const int b_cad = sub & 1;

    if (blockIdx.x < 2) {
        // ================= v path: v = relu(bn3(Wv_hi . xT_hi)) =================
        constexpr int STAGE = 32768;
        constexpr int BOFF  = 16384;
        const int n0 = blockIdx.x * 128;
        const int m0 = blockIdx.y * 128;

        const __nv_bfloat16* A_hi = g_wv_hi;
        const __nv_bfloat16* B_hi = g_xT_hi + (size_t)b * NSEQ * CC;

        auto load_slab = [&](int k0, int buf) {
            const u32 sb = sbase + buf * STAGE;
#pragma unroll
            for (int i = 0; i < 8; i++) {
                int idx = tid + i * 128;
                int row = idx >> 3, c = idx & 7;
                u32 dst = sb + row * 128 + ((c ^ (row & 7)) << 4);
                cp16(dst, A_hi + (size_t)(m0 + row) * CC + k0 + c * 8);
            }
#pragma unroll
            for (int i = 0; i < 8; i++) {
                int idx = tid + i * 128;
                int row = idx >> 3, c = idx & 7;
                u32 dst = sb + BOFF + row * 128 + ((c ^ (row & 7)) << 4);
                cp16(dst, B_hi + (size_t)(n0 + row) * CC + k0 + c * 8);
            }
            cp_commit();
        };

        float acc[4][8][4];
#pragma unroll
        for (int i = 0; i < 4; i++)
#pragma unroll
            for (int j = 0; j < 8; j++)
#pragma unroll
                for (int e = 0; e < 4; e++) acc[i][j][e] = 0.f;

        load_slab(0, 0);

        for (int s = 0; s < 16; s++) {
            if (s + 1 < 16) { load_slab((s + 1) * 64, (s + 1) & 1); cp_wait1(); }
            else            { cp_wait0(); }
            __syncthreads();

            const u32 sb = sbase + (s & 1) * STAGE;
#pragma unroll
            for (int kk = 0; kk < 4; kk++) {
                u32 bh[4][4];
#pragma unroll
                for (int np = 0; np < 4; np++) {
                    u32 badr = sb + BOFF + (b_row + np * 16) * 128
                             + (((kk * 2 + b_cad) ^ lr) << 4);
                    ldsm4(badr, bh[np][0], bh[np][1], bh[np][2], bh[np][3]);
                }
#pragma unroll
                for (int mt = 0; mt < 4; mt++) {
                    u32 ah[4];
                    u32 aadr = sb + (a_row + mt * 16) * 128
                             + (((kk * 2 + a_cad) ^ lr) << 4);
                    ldsm4(aadr, ah[0], ah[1], ah[2], ah[3]);
#pragma unroll
                    for (int np = 0; np < 4; np++) {
                        mma_bf16(acc[mt][2 * np],     ah, bh[np][0], bh[np][1]);
                        mma_bf16(acc[mt][2 * np + 1], ah, bh[np][2], bh[np][3]);
                    }
                }
            }
            __syncthreads();
        }

        float sc[4][2], bs[4][2];
#pragma unroll
        for (int mt = 0; mt < 4; mt++)
#pragma unroll
            for (int h = 0; h < 2; h++) {
                int m = m0 + wm * 64 + mt * 16 + (lane >> 2) + h * 8;
                float s = gA[m] * rsqrtf(vA[m] + EPS_BN);
                sc[mt][h] = s;
                bs[mt][h] = bA[m] - mA[m] * s;
            }

        __nv_bfloat16* Th = (__nv_bfloat16*)smem;
        const int mloc = wm * 64 + (lane >> 2);
        const int nbas = wn * 64 + (lane & 3) * 2;
#pragma unroll
        for (int mt = 0; mt < 4; mt++)
#pragma unroll
            for (int jj = 0; jj < 8; jj++)
#pragma unroll
                for (int e = 0; e < 4; e++) {
                    int h = e >> 1, col = e & 1;
                    float val = fmaxf(acc[mt][jj][e] * sc[mt][h] + bs[mt][h], 0.f);
                    int off = (nbas + jj * 8 + col) * 136 + mloc + mt * 16 + h * 8;
                    Th[off] = __float2bfloat16(val);
                }
        __syncthreads();

#pragma unroll
        for (int i = 0; i < 16; i++) {
            int idx = tid + i * 128;
            int n = idx >> 4, ch = idx & 15;
            uint4 hv = *(uint4*)&Th[n * 136 + ch * 8];
            size_t dst = ((size_t)b * NSEQ + n0 + n) * CC + m0 + ch * 8;
            *(uint4*)&g_vT_hi[dst] = hv;
        }
        return;
    }

    // ================= sim path: exp(-kT.qT^T), unnormalized =================
    {
        const int dt = blockIdx.x - 2;
        const int c0 = blockIdx.y * 128;
        const int d0 = dt * 128;

        const __nv_bfloat16* Ah = g_kT_hi + ((size_t)b * CC + c0) * DQ;
        const __nv_bfloat16* Al = g_kT_lo + ((size_t)b * CC + c0) * DQ;
        const __nv_bfloat16* Bh = g_qT_hi + ((size_t)b * CC + d0) * DQ;
        const __nv_bfloat16* Bl = g_qT_lo + ((size_t)b * CC + d0) * DQ;

#pragma unroll
        for (int i = 0; i < 8; i++) {
            int idx = tid + i * 128;
            int row = idx >> 3, c = idx & 7;
            u32 dst = sbase + row * 128 + ((c ^ (row & 7)) << 4);
            cp16(dst,         Ah + (size_t)row * DQ + c * 8);
            cp16(dst + 16384, Al + (size_t)row * DQ + c * 8);
            cp16(dst + 32768, Bh + (size_t)row * DQ + c * 8);
            cp16(dst + 49152, Bl + (size_t)row * DQ + c * 8);
        }
        cp_commit();
        cp_wait0();
        __syncthreads();

        float acc[4][8][4];
#pragma unroll
        for (int i = 0; i < 4; i++)
#pragma unroll
            for (int j = 0; j < 8; j++)
#pragma unroll
                for (int e = 0; e < 4; e++) acc[i][j][e] = 0.f;

#pragma unroll
        for (int kk = 0; kk < 4; kk++) {
            u32 bh[4][4], bl[4][4];
#pragma unroll
            for (int np = 0; np < 4; np++) {
                u32 badr = sbase + 32768 + (b_row + np * 16) * 128
                         + (((kk * 2 + b_cad) ^ lr) << 4);
                ldsm4(badr,         bh[np][0], bh[np][1], bh[np][2], bh[np][3]);
                ldsm4(badr + 16384, bl[np][0], bl[np][1], bl[np][2], bl[np][3]);
            }
#pragma unroll
            for (int mt = 0; mt < 4; mt++) {
                u32 ah[4], al[4];
                u32 aadr = sbase + (a_row + mt * 16) * 128
                         + (((kk * 2 + a_cad) ^ lr) << 4);
                ldsm4(aadr,         ah[0], ah[1], ah[2], ah[3]);
                ldsm4(aadr + 16384, al[0], al[1], al[2], al[3]);
#pragma unroll
                for (int np = 0; np < 4; np++) {
                    mma_bf16(acc[mt][2 * np],     ah, bh[np][0], bh[np][1]);
                    mma_bf16(acc[mt][2 * np + 1], ah, bh[np][2], bh[np][3]);
                    mma_bf16(acc[mt][2 * np],     al, bh[np][0], bh[np][1]);
                    mma_bf16(acc[mt][2 * np + 1], al, bh[np][2], bh[np][3]);
                    mma_bf16(acc[mt][2 * np],     ah, bl[np][0], bl[np][1]);
                    mma_bf16(acc[mt][2 * np + 1], ah, bl[np][2], bl[np][3]);
                }
            }
        }
        __syncthreads();

        __nv_bfloat16* st   = (__nv_bfloat16*)smem;        // [128][144]
        float*         sums = (float*)(smem + 36864);      // [128][2]
        const int grp = lane >> 2, qt = lane & 3;

#pragma unroll
        for (int mt = 0; mt < 4; mt++)
#pragma unroll
            for (int h = 0; h < 2; h++) {
                int r = wm * 64 + mt * 16 + grp + h * 8;
                float s = 0.f;
#pragma unroll
                for (int jj = 0; jj < 8; jj++) {
                    float e0 = __expf(-acc[mt][jj][2 * h]);
                    float e1 = __expf(-acc[mt][jj][2 * h + 1]);
                    s += e0 + e1;
                    __nv_bfloat162 p;
                    p.x = __float2bfloat16(e0);
                    p.y = __float2bfloat16(e1);
                    *(__nv_bfloat162*)&st[r * 144 + wn * 64 + jj * 8 + qt * 2] = p;
                }
                s += __shfl_xor_sync(~0u, s, 1);
                s += __shfl_xor_sync(~0u, s, 2);
                if (qt == 0) sums[r * 2 + wn] = s;
            }
        __syncthreads();

        {
            float S = sums[tid * 2] + sums[tid * 2 + 1];
            g_psum[((size_t)b * CC + c0 + tid) * 8 + dt] = S;
        }

#pragma unroll
        for (int i = 0; i < 16; i++) {
            int idx = tid + i * 128;
            int row = idx >> 4, ch = idx & 15;
            uint4 v = *(uint4*)&st[row * 144 + ch * 8];
            *(uint4*)&g_aff_hi[((size_t)b * CC + c0 + row) * CC + d0 + ch * 8] = v;
        }
    }
}

// =====================================================================
// out_mma: out = (alpha/S_m)*(exp . vT) + x. 128 thr, 2 CTAs/SM.
// grid (NSEQ/128, CC/128, BB)
// =====================================================================
__global__ void __launch_bounds__(128, 2) out_mma(
    float* __restrict__ Cout, const float* __restrict__ xres,
    const float* __restrict__ alpha)
{
    constexpr int STAGE = 32768;
    constexpr int BOFF  = 16384;

    extern __shared__ __align__(1024) char smem[];
    const u32 sbase = smem_u32(smem);
    const int tid = threadIdx.x;
    const int b   = blockIdx.z;
    const int n0  = blockIdx.x * 128;
    const int m0  = blockIdx.y * 128;

    const __nv_bfloat16* A_hi = g_aff_hi + (size_t)b * CC * CC;
    const __nv_bfloat16* B_hi = g_vT_hi + (size_t)b * NSEQ * CC;

    auto load_slab = [&](int k0, int buf) {
        const u32 sb = sbase + buf * STAGE;
#pragma unroll
        for (int i = 0; i < 8; i++) {
            int idx = tid + i * 128;
            int row = idx >> 3, c = idx & 7;
            u32 dst = sb + row * 128 + ((c ^ (row & 7)) << 4);
            cp16(dst, A_hi + (size_t)(m0 + row) * CC + k0 + c * 8);
        }
#pragma unroll
        for (int i = 0; i < 8; i++) {
            int idx = tid + i * 128;
            int row = idx >> 3, c = idx & 7;
            u32 dst = sb + BOFF + row * 128 + ((c ^ (row & 7)) << 4);
            cp16(dst, B_hi + (size_t)(n0 + row) * CC + k0 + c * 8);
        }
        cp_commit();
    };

    const int lane = tid & 31;
    const int lr   = lane & 7;
    const int sub  = lane >> 3;
    const int warp = tid >> 5;
    const int wm   = warp >> 1, wn = warp & 1;

    const int a_row = wm * 64 + lr + (sub & 1) * 8;
    const int a_cad = sub >> 1;
    const int b_row = wn * 64 + lr + (sub >> 1) * 8;
    const int b_cad = sub & 1;

    float acc[4][8][4];
#pragma unroll
    for (int i = 0; i < 4; i++)
#pragma unroll
        for (int j = 0; j < 8; j++)
#pragma unroll
            for (int e = 0; e < 4; e++) acc[i][j][e] = 0.f;

    load_slab(0, 0);

    for (int s = 0; s < 16; s++) {
        if (s + 1 < 16) { load_slab((s + 1) * 64, (s + 1) & 1); cp_wait1(); }
        else            { cp_wait0(); }
        __syncthreads();

        const u32 sb = sbase + (s & 1) * STAGE;
#pragma unroll
        for (int kk = 0; kk < 4; kk++) {
            u32 bh[4][4];
#pragma unroll
            for (int np = 0; np < 4; np++) {
                u32 badr = sb + BOFF + (b_row + np * 16) * 128
                         + (((kk * 2 + b_cad) ^ lr) << 4);
                ldsm4(badr, bh[np][0], bh[np][1], bh[np][2], bh[np][3]);
            }
#pragma unroll
            for (int mt = 0; mt < 4; mt++) {
                u32 ah[4];
                u32 aadr = sb + (a_row + mt * 16) * 128
                         + (((kk * 2 + a_cad) ^ lr) << 4);
                ldsm4(aadr, ah[0], ah[1], ah[2], ah[3]);
#pragma unroll
                for (int np = 0; np < 4; np++) {
                    mma_bf16(acc[mt][2 * np],     ah, bh[np][0], bh[np][1]);
                    mma_bf16(acc[mt][2 * np + 1], ah, bh[np][2], bh[np][3]);
                }
            }
        }
        __syncthreads();
    }

    const float al_ = alpha[0];
    float scl[4][2];
#pragma unroll
    for (int mt = 0; mt < 4; mt++)
#pragma unroll
        for (int h = 0; h < 2; h++) {
            int m = m0 + wm * 64 + mt * 16 + (lane >> 2) + h * 8;
            const float4* p = (const float4*)&g_psum[((size_t)b * CC + m) * 8];
            float4 u = p[0], v = p[1];
            float S = (u.x + u.y) + (u.z + u.w) + (v.x + v.y) + (v.z + v.w);
            scl[mt][h] = al_ / S;
        }
#pragma unroll
    for (int mt = 0; mt < 4; mt++) {
        int m = m0 + wm * 64 + mt * 16 + (lane >> 2);
#pragma unroll
        for (int jj = 0; jj < 8; jj++) {
            int nn = n0 + wn * 64 + (lane & 3) * 2 + jj * 8;
            size_t b0i = ((size_t)b * CC + m) * NSEQ + nn;
            size_t b1i = b0i + 8 * NSEQ;
            float2 x0 = *(const float2*)&xres[b0i];
            float2 x1 = *(const float2*)&xres[b1i];
            float2 o0, o1;
            o0.x = scl[mt][0] * acc[mt][jj][0] + x0.x;
            o0.y = scl[mt][0] * acc[mt][jj][1] + x0.y;
            o1.x = scl[mt][1] * acc[mt][jj][2] + x1.x;
            o1.y = scl[mt][1] * acc[mt][jj][3] + x1.y;
            *(float2*)&Cout[b0i] = o0;
            *(float2*)&Cout[b1i] = o1;
        }
    }
}

// =====================================================================
extern "C" void kernel_launch(void* const* d_in, const int* in_sizes, int n_in,
                              void* d_out, int out_size)
{
    const float* x    = (const float*)d_in[0];
    const float* Wq   = (const float*)d_in[1];
    const float* Wk   = (const float*)d_in[2];
    const float* Wv   = (const float*)d_in[3];
    const float* bn1g = (const float*)d_in[4];
    const float* bn1b = (const float*)d_in[5];
    const float* bn1m = (const float*)d_in[6];
    const float* bn1v = (const float*)d_in[7];
    const float* bn2g = (const float*)d_in[8];
    const float* bn2b = (const float*)d_in[9];
    const float* bn2m = (const float*)d_in[10];
    const float* bn2v = (const float*)d_in[11];
    const float* bn3g = (const float*)d_in[12];
    const float* bn3b = (const float*)d_in[13];
    const float* bn3m = (const float*)d_in[14];
    const float* bn3v = (const float*)d_in[15];
    const float* alpha= (const float*)d_in[16];
    float* out = (float*)d_out;

    cudaFuncSetAttribute(qk_mma,  cudaFuncAttributeMaxDynamicSharedMemorySize, 196608);
    cudaFuncSetAttribute(v_sim,   cudaFuncAttributeMaxDynamicSharedMemorySize, 65536);
    cudaFuncSetAttribute(out_mma, cudaFuncAttributeMaxDynamicSharedMemorySize, 65536);

    // all dtype conversions (x, Wv, Wq/Wk) in one launch
    convert_all<<<9344, 256>>>(x, Wv, Wq, Wk);

    // qk: q,k = relu(bn([Wq;Wk] . x^T)) -> qT/kT hi/lo
    qk_mma<<<dim3(4, 1, BB), 256, 196608>>>(
        bn1g, bn1b, bn1m, bn1v, bn2g, bn2b, bn2m, bn2v);

    // v (bn3+relu -> vT_hi) and sim (unnormalized exp + psum) in one launch
    v_sim<<<dim3(10, 8, BB), 128, 65536>>>(bn3g, bn3b, bn3m, bn3v);

    // out = (alpha/S)*(exp . vT) + x
    out_mma<<<dim3(NSEQ / 128, CC / 128, BB), 128, 65536>>>(out, x, alpha);
}

// round 12
// speedup vs baseline: 1.2873x; 1.0955x over previous
#include <cuda_runtime.h>
#include <cuda_bf16.h>
#include <cstdint>

#define BB   32
#define CC   1024
#define NSEQ 256
#define DQ   64
#define EPS_BN 1e-5f

typedef unsigned long long u64;
typedef unsigned int u32;

// ---------------- scratch (static device memory) ----------------
__device__ __nv_bfloat16 g_x_hi[(size_t)BB * CC * NSEQ];
__device__ __nv_bfloat16 g_x_lo[(size_t)BB * CC * NSEQ];
__device__ __nv_bfloat16 g_xT_hi[(size_t)BB * NSEQ * CC];
__device__ __nv_bfloat16 g_wv_hi[(size_t)CC * CC];
__device__ __nv_bfloat16 g_wqk_hi[128 * NSEQ];
__device__ __nv_bfloat16 g_wqk_lo[128 * NSEQ];
__device__ __nv_bfloat16 g_qT_hi[(size_t)BB * CC * DQ];
__device__ __nv_bfloat16 g_qT_lo[(size_t)BB * CC * DQ];
__device__ __nv_bfloat16 g_kT_hi[(size_t)BB * CC * DQ];
__device__ __nv_bfloat16 g_kT_lo[(size_t)BB * CC * DQ];
__device__ __nv_bfloat16 g_aff_hi[(size_t)BB * CC * CC];    // UNNORMALIZED exp
__device__ float         g_psum[(size_t)BB * CC * 8];
__device__ __nv_bfloat16 g_vT_hi[(size_t)BB * NSEQ * CC];

// ---------------- helpers ----------------
__device__ __forceinline__ u32 smem_u32(const void* p) {
    u32 a;
    asm("{ .reg .u64 t; cvta.to.shared.u64 t, %1; cvt.u32.u64 %0, t; }"
        : "=r"(a) : "l"(p));
    return a;
}
__device__ __forceinline__ void split_bf16(float v, __nv_bfloat16& h, __nv_bfloat16& l) {
    h = __float2bfloat16(v);
    l = __float2bfloat16(v - __bfloat162float(h));
}
__device__ __forceinline__ void cp16(u32 dst, const void* src) {
    asm volatile("cp.async.cg.shared.global [%0], [%1], 16;" :: "r"(dst), "l"(src));
}
__device__ __forceinline__ void cp_commit() {
    asm volatile("cp.async.commit_group;" ::: "memory");
}
__device__ __forceinline__ void cp_wait1() {
    asm volatile("cp.async.wait_group 1;" ::: "memory");
}
__device__ __forceinline__ void cp_wait0() {
    asm volatile("cp.async.wait_group 0;" ::: "memory");
}
__device__ __forceinline__ void ldsm4(u32 addr, u32& r0, u32& r1, u32& r2, u32& r3) {
    asm volatile("ldmatrix.sync.aligned.m8n8.x4.shared.b16 {%0,%1,%2,%3}, [%4];"
                 : "=r"(r0), "=r"(r1), "=r"(r2), "=r"(r3) : "r"(addr));
}
__device__ __forceinline__ void mma_bf16(float* c, const u32* a, u32 b0, u32 b1) {
    asm volatile(
        "mma.sync.aligned.m16n8k16.row.col.f32.bf16.bf16.f32 "
        "{%0,%1,%2,%3}, {%4,%5,%6,%7}, {%8,%9}, {%0,%1,%2,%3};"
        : "+f"(c[0]), "+f"(c[1]), "+f"(c[2]), "+f"(c[3])
        : "r"(a[0]), "r"(a[1]), "r"(a[2]), "r"(a[3]), "r"(b0), "r"(b1));
}

// =====================================================================
// convert_all (unchanged)
// =====================================================================
__global__ __launch_bounds__(256) void convert_all(
    const float* __restrict__ x,  const float* __restrict__ W,
    const float* __restrict__ Wq, const float* __restrict__ Wk)
{
    __shared__ float t[32][33];
    const int bid = blockIdx.x, tid = threadIdx.x;

    if (bid < 8192) {
        const int tx = tid & 31, ty = tid >> 5;
        const int c0 = (bid & 31) * 32;
        const int n0 = ((bid >> 5) & 7) * 32;
        const int b  = bid >> 8;
#pragma unroll
        for (int r = 0; r < 4; r++) {
            int row = ty + r * 8;
            size_t off = ((size_t)b * CC + c0 + row) * NSEQ + n0 + tx;
            float v = x[off];
            t[row][tx] = v;
            __nv_bfloat16 h, l; split_bf16(v, h, l);
            g_x_hi[off] = h;
            g_x_lo[off] = l;
        }
        __syncthreads();
#pragma unroll
        for (int r = 0; r < 4; r++) {
            int nrow = ty + r * 8;
            g_xT_hi[((size_t)b * NSEQ + n0 + nrow) * CC + c0 + tx] =
                __float2bfloat16(t[tx][nrow]);
        }
    } else if (bid < 9216) {
        size_t i = (size_t)(bid - 8192) * 256 + tid;
        float4 v = ((const float4*)W)[i];
        __nv_bfloat162* hp = (__nv_bfloat162*)g_wv_hi;
        __nv_bfloat162 a; a.x = __float2bfloat16(v.x); a.y = __float2bfloat16(v.y);
        __nv_bfloat162 bq; bq.x = __float2bfloat16(v.z); bq.y = __float2bfloat16(v.w);
        hp[i * 2] = a; hp[i * 2 + 1] = bq;
    } else {
        int r = bid - 9216;
        const float* src = (r < 64) ? (Wq + (size_t)r * NSEQ)
                                    : (Wk + (size_t)(r - 64) * NSEQ);
        float v = src[tid];
        __nv_bfloat16 h, l; split_bf16(v, h, l);
        g_wqk_hi[r * NSEQ + tid] = h;
        g_wqk_lo[r * NSEQ + tid] = l;
    }
}

// =====================================================================
// qk GEMM (3-pass, 256 threads) — unchanged
// =====================================================================
__global__ void __launch_bounds__(256, 1) qk_mma(
    const float* __restrict__ gA, const float* __restrict__ bA,
    const float* __restrict__ mA, const float* __restrict__ vA,
    const float* __restrict__ gB, const float* __restrict__ bB,
    const float* __restrict__ mB, const float* __restrict__ vB)
{
    constexpr int STAGE = 98304;
    constexpr int BOFF  = 32768;

    extern __shared__ __align__(1024) char smem[];
    const u32 sbase = smem_u32(smem);
    const int tid = threadIdx.x;
    const int b   = blockIdx.z;
    const int n0  = blockIdx.x * 256;
    const int m0  = 0;

    const __nv_bfloat16 *A_hi = g_wqk_hi, *A_lo = g_wqk_lo;
    const __nv_bfloat16 *B_hi = g_x_hi + (size_t)b * CC * NSEQ;
    const __nv_bfloat16 *B_lo = g_x_lo + (size_t)b * CC * NSEQ;
    const int lda = NSEQ, ldb = NSEQ;

    auto load_slab = [&](int k0, int buf) {
        const u32 sb = sbase + buf * STAGE;
#pragma unroll
        for (int i = 0; i < 4; i++) {
            int idx = tid + i * 256;
            int row = idx >> 3, c = idx & 7;
            u32 dst = sb + row * 128 + ((c ^ (row & 7)) << 4);
            cp16(dst,         A_hi + (size_t)(m0 + row) * lda + k0 + c * 8);
            cp16(dst + 16384, A_lo + (size_t)(m0 + row) * lda + k0 + c * 8);
        }
#pragma unroll
        for (int i = 0; i < 8; i++) {
            int idx = tid + i * 256;
            int row = idx >> 3, c = idx & 7;
            u32 dst = sb + BOFF + row * 128 + ((c ^ (row & 7)) << 4);
            cp16(dst,         B_hi + (size_t)(n0 + row) * ldb + k0 + c * 8);
            cp16(dst + 32768, B_lo + (size_t)(n0 + row) * ldb + k0 + c * 8);
        }
        cp_commit();
    };

    const int lane = tid & 31;
    const int lr   = lane & 7;
    const int sub  = lane >> 3;
    const int warp = tid >> 5;
    const int wm   = warp >> 2, wn = warp & 3;

    const int a_row = wm * 64 + lr + (sub & 1) * 8;
    const int a_cad = sub >> 1;
    const int b_row = wn * 64 + lr + (sub >> 1) * 8;
    const int b_cad = sub & 1;

    float acc[4][8][4];
#pragma unroll
    for (int i = 0; i < 4; i++)
#pragma unroll
        for (int j = 0; j < 8; j++)
#pragma unroll
            for (int e = 0; e < 4; e++) acc[i][j][e] = 0.f;

    load_slab(0, 0);

    for (int s = 0; s < 4; s++) {
        if (s + 1 < 4) { load_slab((s + 1) * 64, (s + 1) & 1); cp_wait1(); }
        else           { cp_wait0(); }
        __syncthreads();

        const u32 sb = sbase + (s & 1) * STAGE;
#pragma unroll
        for (int kk = 0; kk < 4; kk++) {
            u32 bh[4][4], bl[4][4];
#pragma unroll
            for (int np = 0; np < 4; np++) {
                u32 badr = sb + BOFF + (b_row + np * 16) * 128
                         + (((kk * 2 + b_cad) ^ lr) << 4);
                ldsm4(badr,         bh[np][0], bh[np][1], bh[np][2], bh[np][3]);
                ldsm4(badr + 32768, bl[np][0], bl[np][1], bl[np][2], bl[np][3]);
            }
#pragma unroll
            for (int mt = 0; mt < 4; mt++) {
                u32 ah[4], al[4];
                u32 aadr = sb + (a_row + mt * 16) * 128
                         + (((kk * 2 + a_cad) ^ lr) << 4);
                ldsm4(aadr,         ah[0], ah[1], ah[2], ah[3]);
                ldsm4(aadr + 16384, al[0], al[1], al[2], al[3]);
#pragma unroll
                for (int np = 0; np < 4; np++) {
                    mma_bf16(acc[mt][2 * np],     ah, bh[np][0], bh[np][1]);
                    mma_bf16(acc[mt][2 * np + 1], ah, bh[np][2], bh[np][3]);
                    mma_bf16(acc[mt][2 * np],     al, bh[np][0], bh[np][1]);
                    mma_bf16(acc[mt][2 * np + 1], al, bh[np][2], bh[np][3]);
                    mma_bf16(acc[mt][2 * np],     ah, bl[np][0], bl[np][1]);
                    mma_bf16(acc[mt][2 * np + 1], ah, bl[np][2], bl[np][3]);
                }
            }
        }
        __syncthreads();
    }

    float sc[4][2], bs[4][2];
#pragma unroll
    for (int mt = 0; mt < 4; mt++)
#pragma unroll
        for (int h = 0; h < 2; h++) {
            int o = wm * 64 + mt * 16 + (lane >> 2) + h * 8;
            float g, be, mn, vr;
            if (o < 64) { g = gA[o]; be = bA[o]; mn = mA[o]; vr = vA[o]; }
            else        { g = gB[o - 64]; be = bB[o - 64]; mn = mB[o - 64]; vr = vB[o - 64]; }
            float s = g * rsqrtf(vr + EPS_BN);
            sc[mt][h] = s;
            bs[mt][h] = be - mn * s;
        }

    __nv_bfloat16* Th = (__nv_bfloat16*)smem;
    __nv_bfloat16* Tl = (__nv_bfloat16*)(smem + 69632);
    const int mloc = wm * 64 + (lane >> 2);
    const int nbas = wn * 64 + (lane & 3) * 2;
#pragma unroll
    for (int mt = 0; mt < 4; mt++)
#pragma unroll
        for (int jj = 0; jj < 8; jj++)
#pragma unroll
            for (int e = 0; e < 4; e++) {
                int h = e >> 1, col = e & 1;
                float val = fmaxf(acc[mt][jj][e] * sc[mt][h] + bs[mt][h], 0.f);
                int off = (nbas + jj * 8 + col) * 136 + mloc + mt * 16 + h * 8;
                __nv_bfloat16 hi, lo; split_bf16(val, hi, lo);
                Th[off] = hi;
                Tl[off] = lo;
            }
    __syncthreads();

#pragma unroll
    for (int i = 0; i < 16; i++) {
        int idx = tid + i * 256;
        int n = idx >> 4, ch = idx & 15;
        uint4 hv = *(uint4*)&Th[n * 136 + ch * 8];
        uint4 lv = *(uint4*)&Tl[n * 136 + ch * 8];
        if (ch < 8) {
            size_t dst = ((size_t)b * CC + n0 + n) * DQ + ch * 8;
            *(uint4*)&g_qT_hi[dst] = hv;
            *(uint4*)&g_qT_lo[dst] = lv;
        } else {
            size_t dst = ((size_t)b * CC + n0 + n) * DQ + (ch - 8) * 8;
            *(uint4*)&g_kT_hi[dst] = hv;
            *(uint4*)&g_kT_lo[dst] = lv;
        }
    }
}

// =====================================================================
// v_sim: merged kernel. 128 threads, warp tile 32x64, CTA tile 64x128.
// __launch_bounds__(128,3): 3 CTAs/SM, 48KB smem each.
//  blockIdx.x < 2:  v tile   (n0 = bx*128, m0 = by*64)
//  blockIdx.x >= 2: sim tile (d0 = (bx-2)*128, c0 = by*64)
// grid (10, 16, BB)
// =====================================================================
__global__ void __launch_bounds__(128, 3) v_sim(
    const float* __restrict__ gA, const float* __restrict__ bA,
    const float* __restrict__ mA, const float* __restrict__ vA)
{
    extern __shared__ __align__(1024) char smem[];
    const u32 sbase = smem_u32(smem);
    const int tid  = threadIdx.x;
    const int lane = tid & 31;
    const int lr   = lane & 7;
    const int sub  = lane >> 3;
    const int warp = tid >> 5;
    const int wm   = warp >> 1, wn = warp & 1;
    const int b    = blockIdx.z;

    const int a_row = wm * 32 + lr + (sub & 1) * 8;
    const int a_cad = sub >> 1;
    const int b_row = wn * 64 + lr + (sub >> 1) * 8;
    const int b_cad = sub & 1;

    float acc[2][8][4];
#pragma unroll
    for (int i = 0; i < 2; i++)
#pragma unroll
        for (int j = 0; j < 8; j++)
#pragma unroll
            for (int e = 0; e < 4; e++) acc[i][j][e] = 0.f;

    if (blockIdx.x < 2) {
        // ============ v path: v = relu(bn3(Wv_hi . xT_hi)), tile 64x128 ============
        constexpr int STAGE = 24576;
        constexpr int BOFF  = 8192;
        const int n0 = blockIdx.x * 128;
        const int m0 = blockIdx.y * 64;

        const __nv_bfloat16* A_hi = g_wv_hi;
        const __nv_bfloat16* B_hi = g_xT_hi + (size_t)b * NSEQ * CC;

        auto load_slab = [&](int k0, int buf) {
            const u32 sb = sbase + buf * STAGE;
#pragma unroll
            for (int i = 0; i < 4; i++) {               // A: 64 rows x 8
                int idx = tid + i * 128;
                int row = idx >> 3, c = idx & 7;
                u32 dst = sb + row * 128 + ((c ^ (row & 7)) << 4);
                cp16(dst, A_hi + (size_t)(m0 + row) * CC + k0 + c * 8);
            }
#pragma unroll
            for (int i = 0; i < 8; i++) {               // B: 128 rows x 8
                int idx = tid + i * 128;
                int row = idx >> 3, c = idx & 7;
                u32 dst = sb + BOFF + row * 128 + ((c ^ (row & 7)) << 4);
                cp16(dst, B_hi + (size_t)(n0 + row) * CC + k0 + c * 8);
            }
            cp_commit();
        };

        load_slab(0, 0);

        for (int s = 0; s < 16; s++) {
            if (s + 1 < 16) { load_slab((s + 1) * 64, (s + 1) & 1); cp_wait1(); }
            else            { cp_wait0(); }
            __syncthreads();

            const u32 sb = sbase + (s & 1) * STAGE;
#pragma unroll
            for (int kk = 0; kk < 4; kk++) {
                u32 bh[4][4];
#pragma unroll
                for (int np = 0; np < 4; np++) {
                    u32 badr = sb + BOFF + (b_row + np * 16) * 128
                             + (((kk * 2 + b_cad) ^ lr) << 4);
                    ldsm4(badr, bh[np][0], bh[np][1], bh[np][2], bh[np][3]);
                }
#pragma unroll
                for (int mt = 0; mt < 2; mt++) {
                    u32 ah[4];
                    u32 aadr = sb + (a_row + mt * 16) * 128
                             + (((kk * 2 + a_cad) ^ lr) << 4);
                    ldsm4(aadr, ah[0], ah[1], ah[2], ah[3]);
#pragma unroll
                    for (int np = 0; np < 4; np++) {
                        mma_bf16(acc[mt][2 * np],     ah, bh[np][0], bh[np][1]);
                        mma_bf16(acc[mt][2 * np + 1], ah, bh[np][2], bh[np][3]);
                    }
                }
            }
            __syncthreads();
        }

        float sc[2][2], bs[2][2];
#pragma unroll
        for (int mt = 0; mt < 2; mt++)
#pragma unroll
            for (int h = 0; h < 2; h++) {
                int m = m0 + wm * 32 + mt * 16 + (lane >> 2) + h * 8;
                float s = gA[m] * rsqrtf(vA[m] + EPS_BN);
                sc[mt][h] = s;
                bs[mt][h] = bA[m] - mA[m] * s;
            }

        __nv_bfloat16* Th = (__nv_bfloat16*)smem;   // [128 n][72 m]
        const int mloc = wm * 32 + (lane >> 2);
        const int nbas = wn * 64 + (lane & 3) * 2;
#pragma unroll
        for (int mt = 0; mt < 2; mt++)
#pragma unroll
            for (int jj = 0; jj < 8; jj++)
#pragma unroll
                for (int e = 0; e < 4; e++) {
                    int h = e >> 1, col = e & 1;
                    float val = fmaxf(acc[mt][jj][e] * sc[mt][h] + bs[mt][h], 0.f);
                    int off = (nbas + jj * 8 + col) * 72 + mloc + mt * 16 + h * 8;
                    Th[off] = __float2bfloat16(val);
                }
        __syncthreads();

#pragma unroll
        for (int i = 0; i < 8; i++) {
            int idx = tid + i * 128;
            int n = idx >> 3, ch = idx & 7;
            uint4 hv = *(uint4*)&Th[n * 72 + ch * 8];
            size_t dst = ((size_t)b * NSEQ + n0 + n) * CC + m0 + ch * 8;
            *(uint4*)&g_vT_hi[dst] = hv;
        }
        return;
    }

    // ============ sim path: exp(-kT.qT^T), tile 64x128, 3-pass ============
    {
        const int dt = blockIdx.x - 2;
        const int c0 = blockIdx.y * 64;
        const int d0 = dt * 128;

        const __nv_bfloat16* Ah = g_kT_hi + ((size_t)b * CC + c0) * DQ;
        const __nv_bfloat16* Al = g_kT_lo + ((size_t)b * CC + c0) * DQ;
        const __nv_bfloat16* Bh = g_qT_hi + ((size_t)b * CC + d0) * DQ;
        const __nv_bfloat16* Bl = g_qT_lo + ((size_t)b * CC + d0) * DQ;

        // A hi@0 (8K), A lo@8192, B hi@16384 (16K), B lo@32768 (16K)
#pragma unroll
        for (int i = 0; i < 4; i++) {
            int idx = tid + i * 128;
            int row = idx >> 3, c = idx & 7;
            u32 dst = sbase + row * 128 + ((c ^ (row & 7)) << 4);
            cp16(dst,        Ah + (size_t)row * DQ + c * 8);
            cp16(dst + 8192, Al + (size_t)row * DQ + c * 8);
        }
#pragma unroll
        for (int i = 0; i < 8; i++) {
            int idx = tid + i * 128;
            int row = idx >> 3, c = idx & 7;
            u32 dst = sbase + 16384 + row * 128 + ((c ^ (row & 7)) << 4);
            cp16(dst,         Bh + (size_t)row * DQ + c * 8);
            cp16(dst + 16384, Bl + (size_t)row * DQ + c * 8);
        }
        cp_commit();
        cp_wait0();
        __syncthreads();

#pragma unroll
        for (int kk = 0; kk < 4; kk++) {
            u32 bh[4][4], bl[4][4];
#pragma unroll
            for (int np = 0; np < 4; np++) {
                u32 badr = sbase + 16384 + (b_row + np * 16) * 128
                         + (((kk * 2 + b_cad) ^ lr) << 4);
                ldsm4(badr,         bh[np][0], bh[np][1], bh[np][2], bh[np][3]);
                ldsm4(badr + 16384, bl[np][0], bl[np][1], bl[np][2], bl[np][3]);
            }
#pragma unroll
            for (int mt = 0; mt < 2; mt++) {
                u32 ah[4], al[4];
                u32 aadr = sbase + (a_row + mt * 16) * 128
                         + (((kk * 2 + a_cad) ^ lr) << 4);
                ldsm4(aadr,        ah[0], ah[1], ah[2], ah[3]);
                ldsm4(aadr + 8192, al[0], al[1], al[2], al[3]);
#pragma unroll
                for (int np = 0; np < 4; np++) {
                    mma_bf16(acc[mt][2 * np],     ah, bh[np][0], bh[np][1]);
                    mma_bf16(acc[mt][2 * np + 1], ah, bh[np][2], bh[np][3]);
                    mma_bf16(acc[mt][2 * np],     al, bh[np][0], bh[np][1]);
                    mma_bf16(acc[mt][2 * np + 1], al, bh[np][2], bh[np][3]);
                    mma_bf16(acc[mt][2 * np],     ah, bl[np][0], bl[np][1]);
                    mma_bf16(acc[mt][2 * np + 1], ah, bl[np][2], bl[np][3]);
                }
            }
        }
        __syncthreads();

        __nv_bfloat16* st   = (__nv_bfloat16*)smem;        // [64][144]
        float*         sums = (float*)(smem + 18432);      // [64][2]
        const int grp = lane >> 2, qt = lane & 3;

#pragma unroll
        for (int mt = 0; mt < 2; mt++)
#pragma unroll
            for (int h = 0; h < 2; h++) {
                int r = wm * 32 + mt * 16 + grp + h * 8;
                float s = 0.f;
#pragma unroll
                for (int jj = 0; jj < 8; jj++) {
                    float e0 = __expf(-acc[mt][jj][2 * h]);
                    float e1 = __expf(-acc[mt][jj][2 * h + 1]);
                    s += e0 + e1;
                    __nv_bfloat162 p;
                    p.x = __float2bfloat16(e0);
                    p.y = __float2bfloat16(e1);
                    *(__nv_bfloat162*)&st[r * 144 + wn * 64 + jj * 8 + qt * 2] = p;
                }
                s += __shfl_xor_sync(~0u, s, 1);
                s += __shfl_xor_sync(~0u, s, 2);
                if (qt == 0) sums[r * 2 + wn] = s;
            }
        __syncthreads();

        if (tid < 64) {
            float S = sums[tid * 2] + sums[tid * 2 + 1];
            g_psum[((size_t)b * CC + c0 + tid) * 8 + dt] = S;
        }

#pragma unroll
        for (int i = 0; i < 8; i++) {
            int idx = tid + i * 128;
            int row = idx >> 4, ch = idx & 15;
            uint4 v = *(uint4*)&st[row * 144 + ch * 8];
            *(uint4*)&g_aff_hi[((size_t)b * CC + c0 + row) * CC + d0 + ch * 8] = v;
        }
    }
}

// =====================================================================
// out_mma: out = (alpha/S_m)*(exp . vT) + x. 128 thr, warp tile 32x64,
// CTA tile 64x128, 4 CTAs/SM. grid (2, 16, BB)
// =====================================================================
__global__ void __launch_bounds__(128, 4) out_mma(
    float* __restrict__ Cout, const float* __restrict__ xres,
    const float* __restrict__ alpha)
{
    constexpr int STAGE = 24576;
    constexpr int BOFF  = 8192;

    extern __shared__ __align__(1024) char smem[];
    const u32 sbase = smem_u32(smem);
    const int tid = threadIdx.x;
    const int b   = blockIdx.z;
    const int n0  = blockIdx.x * 128;
    const int m0  = blockIdx.y * 64;

    const __nv_bfloat16* A_hi = g_aff_hi + (size_t)b * CC * CC;
    const __nv_bfloat16* B_hi = g_vT_hi + (size_t)b * NSEQ * CC;

    auto load_slab = [&](int k0, int buf) {
        const u32 sb = sbase + buf * STAGE;
#pragma unroll
        for (int i = 0; i < 4; i++) {
            int idx = tid + i * 128;
            int row = idx >> 3, c = idx & 7;
            u32 dst = sb + row * 128 + ((c ^ (row & 7)) << 4);
            cp16(dst, A_hi + (size_t)(m0 + row) * CC + k0 + c * 8);
        }
#pragma unroll
        for (int i = 0; i < 8; i++) {
            int idx = tid + i * 128;
            int row = idx >> 3, c = idx & 7;
            u32 dst = sb + BOFF + row * 128 + ((c ^ (row & 7)) << 4);
            cp16(dst, B_hi + (size_t)(n0 + row) * CC + k0 + c * 8);
        }
        cp_commit();
    };

    const int lane = tid & 31;
    const int lr   = lane & 7;
    const int sub  = lane >> 3;
    const int warp = tid >> 5;
    const int wm   = warp >> 1, wn = warp & 1;

    const int a_row = wm * 32 + lr + (sub & 1) * 8;
    const int a_cad = sub >> 1;
    const int b_row = wn * 64 + lr + (sub >> 1) * 8;
    const int b_cad = sub & 1;

    float acc[2][8][4];
#pragma unroll
    for (int i = 0; i < 2; i++)
#pragma unroll
        for (int j = 0; j < 8; j++)
#pragma unroll
            for (int e = 0; e < 4; e++) acc[i][j][e] = 0.f;

    load_slab(0, 0);

    for (int s = 0; s < 16; s++) {
        if (s + 1 < 16) { load_slab((s + 1) * 64, (s + 1) & 1); cp_wait1(); }
        else            { cp_wait0(); }
        __syncthreads();

        const u32 sb = sbase + (s & 1) * STAGE;
#pragma unroll
        for (int kk = 0; kk < 4; kk++) {
            u32 bh[4][4];
#pragma unroll
            for (int np = 0; np < 4; np++) {
                u32 badr = sb + BOFF + (b_row + np * 16) * 128
                         + (((kk * 2 + b_cad) ^ lr) << 4);
                ldsm4(badr, bh[np][0], bh[np][1], bh[np][2], bh[np][3]);
            }
#pragma unroll
            for (int mt = 0; mt < 2; mt++) {
                u32 ah[4];
                u32 aadr = sb + (a_row + mt * 16) * 128
                         + (((kk * 2 + a_cad) ^ lr) << 4);
                ldsm4(aadr, ah[0], ah[1], ah[2], ah[3]);
#pragma unroll
                for (int np = 0; np < 4; np++) {
                    mma_bf16(acc[mt][2 * np],     ah, bh[np][0], bh[np][1]);
                    mma_bf16(acc[mt][2 * np + 1], ah, bh[np][2], bh[np][3]);
                }
            }
        }
        __syncthreads();
    }

    const float al_ = alpha[0];
    float scl[2][2];
#pragma unroll
    for (int mt = 0; mt < 2; mt++)
#pragma unroll
        for (int h = 0; h < 2; h++) {
            int m = m0 + wm * 32 + mt * 16 + (lane >> 2) + h * 8;
            const float4* p = (const float4*)&g_psum[((size_t)b * CC + m) * 8];
            float4 u = p[0], v = p[1];
            float S = (u.x + u.y) + (u.z + u.w) + (v.x + v.y) + (v.z + v.w);
            scl[mt][h] = al_ / S;
        }
#pragma unroll
    for (int mt = 0; mt < 2; mt++) {
        int m = m0 + wm * 32 + mt * 16 + (lane >> 2);
#pragma unroll
        for (int jj = 0; jj < 8; jj++) {
            int nn = n0 + wn * 64 + (lane & 3) * 2 + jj * 8;
            size_t b0i = ((size_t)b * CC + m) * NSEQ + nn;
            size_t b1i = b0i + 8 * NSEQ;
            float2 x0 = *(const float2*)&xres[b0i];
            float2 x1 = *(const float2*)&xres[b1i];
            float2 o0, o1;
            o0.x = scl[mt][0] * acc[mt][jj][0] + x0.x;
            o0.y = scl[mt][0] * acc[mt][jj][1] + x0.y;
            o1.x = scl[mt][1] * acc[mt][jj][2] + x1.x;
            o1.y = scl[mt][1] * acc[mt][jj][3] + x1.y;
            *(float2*)&Cout[b0i] = o0;
            *(float2*)&Cout[b1i] = o1;
        }
    }
}

// =====================================================================
extern "C" void kernel_launch(void* const* d_in, const int* in_sizes, int n_in,
                              void* d_out, int out_size)
{
    const float* x    = (const float*)d_in[0];
    const float* Wq   = (const float*)d_in[1];
    const float* Wk   = (const float*)d_in[2];
    const float* Wv   = (const float*)d_in[3];
    const float* bn1g = (const float*)d_in[4];
    const float* bn1b = (const float*)d_in[5];
    const float* bn1m = (const float*)d_in[6];
    const float* bn1v = (const float*)d_in[7];
    const float* bn2g = (const float*)d_in[8];
    const float* bn2b = (const float*)d_in[9];
    const float* bn2m = (const float*)d_in[10];
    const float* bn2v = (const float*)d_in[11];
    const float* bn3g = (const float*)d_in[12];
    const float* bn3b = (const float*)d_in[13];
    const float* bn3m = (const float*)d_in[14];
    const float* bn3v = (const float*)d_in[15];
    const float* alpha= (const float*)d_in[16];
    float* out = (float*)d_out;

    cudaFuncSetAttribute(qk_mma,  cudaFuncAttributeMaxDynamicSharedMemorySize, 196608);
    cudaFuncSetAttribute(v_sim,   cudaFuncAttributeMaxDynamicSharedMemorySize, 49152);
    cudaFuncSetAttribute(out_mma, cudaFuncAttributeMaxDynamicSharedMemorySize, 49152);

    convert_all<<<9344, 256>>>(x, Wv, Wq, Wk);

    qk_mma<<<dim3(4, 1, BB), 256, 196608>>>(
        bn1g, bn1b, bn1m, bn1v, bn2g, bn2b, bn2m, bn2v);

    v_sim<<<dim3(10, 16, BB), 128, 49152>>>(bn3g, bn3b, bn3m, bn3v);

    out_mma<<<dim3(2, 16, BB), 128, 49152>>>(out, x, alpha);
}